// round 11
// baseline (speedup 1.0000x reference)
#include <cuda_runtime.h>
#include <cuda_bf16.h>
#include <math.h>
#include <stdint.h>

// Problem constants
#define BB 4
#define CC 96
#define HWSZ 65536
#define NHEAD 8
#define CPH 12
#define NTOT (BB*CC*HWSZ)
#define BNCNT (BB*NHEAD)
#define SSZ (BNCNT*HWSZ)

// ----------------- scratch -----------------
__device__ float g_x1ln[NTOT];
__device__ float g_x2ln[NTOT];
__device__ float g_tmp [NTOT];
__device__ float g_tmp2[NTOT];
__device__ float g_M   [NTOT];
__device__ float g_S1  [SSZ];
__device__ float g_S2  [SSZ];
__device__ float g_nsq  [4][BNCNT*256];
__device__ float g_scale[4][BNCNT*256];

// bf16 split buffers (hi/lo)
__device__ __nv_bfloat16 g_X1h[NTOT], g_X1l[NTOT];
__device__ __nv_bfloat16 g_X2h[NTOT], g_X2l[NTOT];
__device__ __nv_bfloat16 g_O1h[NTOT], g_O1l[NTOT];
__device__ __nv_bfloat16 g_O2h[NTOT], g_O2l[NTOT];
__device__ __nv_bfloat16 g_X1Th[NTOT], g_X1Tl[NTOT];
__device__ __nv_bfloat16 g_X2Th[NTOT], g_X2Tl[NTOT];
__device__ __nv_bfloat16 g_O1Th[NTOT], g_O1Tl[NTOT];
__device__ __nv_bfloat16 g_O2Th[NTOT], g_O2Tl[NTOT];
__device__ __nv_bfloat16 g_P1h[SSZ], g_P1l[SSZ];
__device__ __nv_bfloat16 g_P2h[SSZ], g_P2l[SSZ];

// ----------------- small helpers -----------------
__device__ __forceinline__ void split_store(float v, __nv_bfloat16* hi, __nv_bfloat16* lo, long idx)
{
    __nv_bfloat16 h = __float2bfloat16(v);
    hi[idx] = h;
    lo[idx] = __float2bfloat16(v - __bfloat162float(h));
}

__device__ __forceinline__ void split2(float a, float b, uint32_t& h, uint32_t& l)
{
    __nv_bfloat162 hv = __floats2bfloat162_rn(a, b);
    h = *(uint32_t*)&hv;
    __nv_bfloat162 lv = __floats2bfloat162_rn(a - __bfloat162float(hv.x),
                                              b - __bfloat162float(hv.y));
    l = *(uint32_t*)&lv;
}

__device__ __forceinline__ float2 upk2(uint32_t h, uint32_t l)
{
    __nv_bfloat162 hh = *(__nv_bfloat162*)&h;
    __nv_bfloat162 ll = *(__nv_bfloat162*)&l;
    return make_float2(__bfloat162float(hh.x) + __bfloat162float(ll.x),
                       __bfloat162float(hh.y) + __bfloat162float(ll.y));
}

// ----------------- LayerNorm (channel dim), smem-cached, fused bf16 split -----------------
__global__ void ln_kernel(const float* __restrict__ x, const float* __restrict__ w,
                          const float* __restrict__ bsh, float* __restrict__ y,
                          __nv_bfloat16* __restrict__ hi, __nv_bfloat16* __restrict__ lo)
{
    extern __shared__ float lnsm[];   // 96*256 floats
    int tid = threadIdx.x;
    int pos = blockIdx.x * 256 + tid;
    long base = ((long)blockIdx.y * CC) << 16;
    float s = 0.f, ss = 0.f;
    #pragma unroll 8
    for (int c = 0; c < CC; ++c) {
        float v = x[base + ((long)c << 16) + pos];
        lnsm[c * 256 + tid] = v;
        s += v; ss += v * v;
    }
    float mu = s * (1.f / 96.f);
    float var = ss * (1.f / 96.f) - mu * mu;
    float inv = rsqrtf(var + 1e-5f);
    #pragma unroll 8
    for (int c = 0; c < CC; ++c) {
        long id = base + ((long)c << 16) + pos;
        float v = (lnsm[c * 256 + tid] - mu) * inv * w[c] + bsh[c];
        y[id] = v;
        split_store(v, hi, lo, id);
    }
}

// ----------------- transpose+split (fp32 input) with cheap fused row/col norms -----------------
__global__ void splitT_kernel(const float* __restrict__ X,
                              __nv_bfloat16* __restrict__ hiT, __nv_bfloat16* __restrict__ loT,
                              int rw, int cw)
{
    __shared__ float ts[64][33];
    __shared__ float colacc[32];
    int p = blockIdx.y;                 // plane 0..383
    int b = p / 96, c = p - b * 96, head = c / 12;
    int nbase = (b * 8 + head) * 256;
    long po = (long)p << 16;
    int h0 = (blockIdx.x >> 3) << 6;
    int w0 = (blockIdx.x & 7) << 5;
    int tx = threadIdx.x, ty = threadIdx.y;
    int tid = ty * 32 + tx;
    if (ty == 0) colacc[tx] = 0.f;
    float cs = 0.f;
    #pragma unroll
    for (int i = 0; i < 8; ++i) {
        int r = ty * 8 + i;
        float v = X[po + (long)(h0 + r) * 256 + w0 + tx];
        ts[r][tx] = v;
        cs += v * v;
    }
    __syncthreads();
    if (cw >= 0) atomicAdd(&colacc[tx], cs);
    if (rw >= 0 && tid < 64) {
        float rs = 0.f;
        #pragma unroll
        for (int q = 0; q < 32; ++q) { float v = ts[tid][q]; rs += v * v; }
        atomicAdd(&g_nsq[rw][nbase + h0 + tid], rs);
    }
    uint32_t* hp = (uint32_t*)hiT;
    uint32_t* lp = (uint32_t*)loT;
    #pragma unroll
    for (int j = 0; j < 4; ++j) {
        int wr = ty * 4 + j;
        float v0 = ts[2 * tx][wr], v1 = ts[2 * tx + 1][wr];
        uint32_t h, l; split2(v0, v1, h, l);
        long oidx = (po + (long)(w0 + wr) * 256 + h0) >> 1;
        hp[oidx + tx] = h;
        lp[oidx + tx] = l;
    }
    if (cw >= 0) {
        __syncthreads();
        if (ty == 0) atomicAdd(&g_nsq[cw][nbase + w0 + tx], colacc[tx]);
    }
}

// ----------------- transpose+split (pair input) with cheap fused row/col norms -----------------
__global__ void splitT_pair_kernel(const __nv_bfloat16* __restrict__ Xh,
                                   const __nv_bfloat16* __restrict__ Xl,
                                   __nv_bfloat16* __restrict__ hiT, __nv_bfloat16* __restrict__ loT,
                                   int rw, int cw)
{
    __shared__ float ts[64][33];
    __shared__ float colacc[32];
    int p = blockIdx.y;
    int b = p / 96, c = p - b * 96, head = c / 12;
    int nbase = (b * 8 + head) * 256;
    long po = (long)p << 16;
    int h0 = (blockIdx.x >> 3) << 6;
    int w0 = (blockIdx.x & 7) << 5;
    int tx = threadIdx.x, ty = threadIdx.y;
    int tid = ty * 32 + tx;
    if (ty == 0) colacc[tx] = 0.f;
    const uint32_t* hp_in = (const uint32_t*)Xh;
    const uint32_t* lp_in = (const uint32_t*)Xl;
    int pr = tx & 15, ro = tx >> 4;
    float cs0 = 0.f, cs1 = 0.f;
    #pragma unroll
    for (int i = 0; i < 4; ++i) {
        int r = ty * 8 + 2 * i + ro;
        long u = (po + (long)(h0 + r) * 256 + w0) >> 1;
        float2 v = upk2(hp_in[u + pr], lp_in[u + pr]);
        ts[r][2 * pr] = v.x;
        ts[r][2 * pr + 1] = v.y;
        cs0 += v.x * v.x; cs1 += v.y * v.y;
    }
    __syncthreads();
    if (cw >= 0) {
        atomicAdd(&colacc[2 * pr], cs0);
        atomicAdd(&colacc[2 * pr + 1], cs1);
    }
    if (rw >= 0 && tid < 64) {
        float rs = 0.f;
        #pragma unroll
        for (int q = 0; q < 32; ++q) { float v = ts[tid][q]; rs += v * v; }
        atomicAdd(&g_nsq[rw][nbase + h0 + tid], rs);
    }
    uint32_t* hp = (uint32_t*)hiT;
    uint32_t* lp = (uint32_t*)loT;
    #pragma unroll
    for (int j = 0; j < 4; ++j) {
        int wr = ty * 4 + j;
        float v0 = ts[2 * tx][wr], v1 = ts[2 * tx + 1][wr];
        uint32_t h, l; split2(v0, v1, h, l);
        long oidx = (po + (long)(w0 + wr) * 256 + h0) >> 1;
        hp[oidx + tx] = h;
        lp[oidx + tx] = l;
    }
    if (cw >= 0) {
        __syncthreads();
        if (ty == 0) atomicAdd(&g_nsq[cw][nbase + w0 + tx], colacc[tx]);
    }
}

// ----------------- depthwise (1,7)+(1,11) conv along W, 4 rows/block -----------------
__global__ void dw_kernel(const float* __restrict__ x,
                          const float* __restrict__ w7, const float* __restrict__ b7,
                          const float* __restrict__ w11, const float* __restrict__ b11,
                          float* __restrict__ y)
{
    int hq = blockIdx.x, c = blockIdx.y, b = blockIdx.z;
    long pb = (((long)(b * CC + c)) << 16);
    __shared__ float s[4][272];
    __shared__ float wk[18];
    int tid = threadIdx.x;
    int ty = tid >> 6, tx = tid & 63;
    long rowbase = pb + ((long)(4 * hq + ty) << 8);
    *(float4*)&s[ty][8 + tx * 4] = *(const float4*)&x[rowbase + tx * 4];
    if (tx < 8) { s[ty][tx] = 0.f; s[ty][264 + tx] = 0.f; }
    if (tid < 7) wk[tid] = w7[c * 7 + tid];
    else if (tid < 18) wk[tid] = w11[c * 11 + (tid - 7)];
    __syncthreads();
    float bb = b7[c] + b11[c];
    float o[4];
    #pragma unroll
    for (int u = 0; u < 4; ++u) {
        int wpos = tx * 4 + u;
        float acc = bb;
        #pragma unroll
        for (int k = 0; k < 7; ++k)  acc += s[ty][wpos + 5 + k] * wk[k];
        #pragma unroll
        for (int k = 0; k < 11; ++k) acc += s[ty][wpos + 3 + k] * wk[7 + k];
        o[u] = acc;
    }
    *(float4*)&y[rowbase + tx * 4] = make_float4(o[0], o[1], o[2], o[3]);
}

// ----------------- norm scratch mgmt -----------------
__global__ void zero_kernel()
{
    int i = blockIdx.x * 256 + threadIdx.x;
    if (i < 4 * BNCNT * 256) (&g_nsq[0][0])[i] = 0.f;
}

__global__ void scale_kernel()
{
    int i = blockIdx.x * 256 + threadIdx.x;
    if (i < 4 * BNCNT * 256)
        (&g_scale[0][0])[i] = 1.f / fmaxf(sqrtf((&g_nsq[0][0])[i]), 1e-12f);
}

// ================= mma primitives =================
__device__ __forceinline__ void mma_bf16(float* c, const uint32_t* a, uint32_t b0, uint32_t b1)
{
    asm volatile(
        "mma.sync.aligned.m16n8k16.row.col.f32.bf16.bf16.f32 "
        "{%0,%1,%2,%3},{%4,%5,%6,%7},{%8,%9},{%0,%1,%2,%3};"
        : "+f"(c[0]), "+f"(c[1]), "+f"(c[2]), "+f"(c[3])
        : "r"(a[0]), "r"(a[1]), "r"(a[2]), "r"(a[3]), "r"(b0), "r"(b1));
}

__device__ __forceinline__ void cpa16(uint32_t dst, const void* src)
{
    asm volatile("cp.async.cg.shared.global [%0], [%1], 16;" :: "r"(dst), "l"(src));
}
#define CP_COMMIT() asm volatile("cp.async.commit_group;")
#define CP_WAIT(n)  asm volatile("cp.async.wait_group %0;" :: "n"(n))

// ================= 128x128 bf16-split GEMM core =================
#define KP 20
#define SBUF_OFF (4*128*KP)
#define SMEM_BYTES (8*128*KP*4)

__device__ __forceinline__ void load_stage(int buf, const uint4* ah, const uint4* al,
                                           const uint4* bh, const uint4* bl,
                                           uint32_t smbase, int tid)
{
    #pragma unroll
    for (int i = 0; i < 8; ++i) {
        const int hl  = (i >> 1) & 1;
        const int isB = (i >= 4);
        int r = ((i & 1) << 8) + tid;
        int m = r >> 2, q = r & 3;
        const uint4* src = (isB ? (hl ? bl : bh) : (hl ? al : ah)) + m * 32 + q;
        int w = (((buf * 2 + hl) * 128 + m) * KP + q * 4) + (isB ? SBUF_OFF : 0);
        cpa16(smbase + (w << 2), src);
    }
}

__device__ __forceinline__ void gemm_compute(int buf, float (&acc)[4][4][4],
                                             int wM, int wN, int g, int t)
{
    extern __shared__ uint32_t sm[];
    #pragma unroll
    for (int ks = 0; ks < 2; ++ks) {
        int kq = ks * 8 + t;
        uint32_t bh[4][2], bl[4][2];
        #pragma unroll
        for (int nf = 0; nf < 4; ++nf) {
            int n = wN * 32 + nf * 8 + g;
            const uint32_t* pbh = &sm[SBUF_OFF + ((buf * 2 + 0) * 128 + n) * KP];
            const uint32_t* pbl = &sm[SBUF_OFF + ((buf * 2 + 1) * 128 + n) * KP];
            bh[nf][0] = pbh[kq]; bh[nf][1] = pbh[kq + 4];
            bl[nf][0] = pbl[kq]; bl[nf][1] = pbl[kq + 4];
        }
        #pragma unroll
        for (int mf = 0; mf < 4; ++mf) {
            int rrow = wM * 64 + mf * 16 + g;
            const uint32_t* pah = &sm[((buf * 2 + 0) * 128 + rrow) * KP];
            const uint32_t* pal = &sm[((buf * 2 + 1) * 128 + rrow) * KP];
            uint32_t ah4[4] = { pah[kq], pah[8 * KP + kq], pah[kq + 4], pah[8 * KP + kq + 4] };
            uint32_t al4[4] = { pal[kq], pal[8 * KP + kq], pal[kq + 4], pal[8 * KP + kq + 4] };
            #pragma unroll
            for (int nf = 0; nf < 4; ++nf) {
                mma_bf16(acc[mf][nf], ah4, bh[nf][0], bh[nf][1]);
                mma_bf16(acc[mf][nf], al4, bh[nf][0], bh[nf][1]);
                mma_bf16(acc[mf][nf], ah4, bl[nf][0], bl[nf][1]);
            }
        }
    }
}

__device__ __forceinline__ void gemm_run(float (&acc)[4][4][4],
    const uint4* ah, const uint4* al, const uint4* bh, const uint4* bl,
    int nkt, int ps4, uint32_t smbase, int tid, int wM, int wN, int g, int t)
{
    load_stage(0, ah, al, bh, bl, smbase, tid);
    CP_COMMIT();
    for (int kt = 0; kt < nkt; ++kt) {
        int nx = kt + 1;
        if (nx < nkt) {
            int off = (nx >> 3) * ps4 + (nx & 7) * 4;
            load_stage(nx & 1, ah + off, al + off, bh + off, bl + off, smbase, tid);
            CP_COMMIT();
            CP_WAIT(1);
        } else {
            CP_WAIT(0);
        }
        __syncthreads();
        gemm_compute(kt & 1, acc, wM, wN, g, t);
        __syncthreads();
    }
}

// score: C = A @ B' over 12 planes (K = 3072)
__global__ void __launch_bounds__(256) score_mma(
    const __nv_bfloat16* __restrict__ Ah, const __nv_bfloat16* __restrict__ Al,
    const __nv_bfloat16* __restrict__ Bh, const __nv_bfloat16* __restrict__ Bl,
    float* __restrict__ C)
{
    extern __shared__ uint32_t sm[];
    uint32_t smbase = (uint32_t)__cvta_generic_to_shared(sm);
    int tid = threadIdx.x, lane = tid & 31, wid = tid >> 5;
    int wM = wid >> 2, wN = wid & 3, g = lane >> 2, t = lane & 3;
    int bn = blockIdx.y;
    long po = (long)((bn >> 3) * CC + (bn & 7) * CPH) << 16;
    int row0 = (blockIdx.x >> 1) << 7;
    int col0 = (blockIdx.x & 1) << 7;
    const uint4* ah = (const uint4*)(Ah + po) + row0 * 32;
    const uint4* al = (const uint4*)(Al + po) + row0 * 32;
    const uint4* bh = (const uint4*)(Bh + po) + col0 * 32;
    const uint4* bl = (const uint4*)(Bl + po) + col0 * 32;
    float acc[4][4][4];
    #pragma unroll
    for (int a = 0; a < 4; ++a)
        #pragma unroll
        for (int b = 0; b < 4; ++b)
            #pragma unroll
            for (int d = 0; d < 4; ++d) acc[a][b][d] = 0.f;

    gemm_run(acc, ah, al, bh, bl, 96, 8192, smbase, tid, wM, wN, g, t);

    float* Cp = C + ((long)bn << 16);
    int rbase = row0 + wM * 64 + g;
    int cbase = col0 + wN * 32 + 2 * t;
    #pragma unroll
    for (int mf = 0; mf < 4; ++mf) {
        int r = rbase + mf * 16;
        #pragma unroll
        for (int nf = 0; nf < 4; ++nf) {
            int cc = cbase + nf * 8;
            *(float2*)&Cp[(long)r * 256 + cc] = make_float2(acc[mf][nf][0], acc[mf][nf][1]);
            *(float2*)&Cp[(long)(r + 8) * 256 + cc] = make_float2(acc[mf][nf][2], acc[mf][nf][3]);
        }
    }
}

// av2: M_c = X2_c @ P2' + residual(O2T*s1 + O1T*s2)
__global__ void __launch_bounds__(256) av2_mma(
    const __nv_bfloat16* __restrict__ X2h, const __nv_bfloat16* __restrict__ X2l,
    const __nv_bfloat16* __restrict__ P2h, const __nv_bfloat16* __restrict__ P2l,
    const __nv_bfloat16* __restrict__ O1Th, const __nv_bfloat16* __restrict__ O1Tl,
    const __nv_bfloat16* __restrict__ O2Th, const __nv_bfloat16* __restrict__ O2Tl,
    const float* __restrict__ s1, const float* __restrict__ s2,
    float* __restrict__ M)
{
    extern __shared__ uint32_t sm[];
    uint32_t smbase = (uint32_t)__cvta_generic_to_shared(sm);
    int tid = threadIdx.x, lane = tid & 31, wid = tid >> 5;
    int wM = wid >> 2, wN = wid & 3, g = lane >> 2, t = lane & 3;
    int bn = blockIdx.z, c = blockIdx.y;
    long po = (long)((bn >> 3) * CC + (bn & 7) * CPH + c) << 16;
    long so = (long)bn << 16;
    int row0 = (blockIdx.x >> 1) << 7;
    int col0 = (blockIdx.x & 1) << 7;
    float acc[4][4][4];
    #pragma unroll
    for (int a = 0; a < 4; ++a)
        #pragma unroll
        for (int b = 0; b < 4; ++b)
            #pragma unroll
            for (int d = 0; d < 4; ++d) acc[a][b][d] = 0.f;

    gemm_run(acc, (const uint4*)(X2h + po) + row0 * 32, (const uint4*)(X2l + po) + row0 * 32,
                  (const uint4*)(P2h + so) + col0 * 32, (const uint4*)(P2l + so) + col0 * 32,
             8, 0, smbase, tid, wM, wN, g, t);

    const uint32_t* pO1h = (const uint32_t*)(O1Th + po);
    const uint32_t* pO1l = (const uint32_t*)(O1Tl + po);
    const uint32_t* pO2h = (const uint32_t*)(O2Th + po);
    const uint32_t* pO2l = (const uint32_t*)(O2Tl + po);
    const float* s1p = s1 + bn * 256;
    const float* s2p = s2 + bn * 256;
    float* Mp = M + po;
    int rbase = row0 + wM * 64 + g;
    int cbase = col0 + wN * 32 + 2 * t;
    #pragma unroll
    for (int mf = 0; mf < 4; ++mf) {
        int r = rbase + mf * 16;
        float s1a = s1p[r], s1b = s1p[r + 8];
        #pragma unroll
        for (int nf = 0; nf < 4; ++nf) {
            int cc = cbase + nf * 8;
            float s2a = s2p[cc], s2b = s2p[cc + 1];
            long q0 = ((long)r * 256 + cc) >> 1;
            long q1 = ((long)(r + 8) * 256 + cc) >> 1;
            float2 o1a = upk2(pO1h[q0], pO1l[q0]);
            float2 o2a = upk2(pO2h[q0], pO2l[q0]);
            float2 o1b = upk2(pO1h[q1], pO1l[q1]);
            float2 o2b = upk2(pO2h[q1], pO2l[q1]);
            float v0 = acc[mf][nf][0] + o2a.x * s1a + o1a.x * s2a;
            float v1 = acc[mf][nf][1] + o2a.y * s1a + o1a.y * s2b;
            float v2 = acc[mf][nf][2] + o2b.x * s1b + o1b.x * s2a;
            float v3 = acc[mf][nf][3] + o2b.y * s1b + o1b.y * s2b;
            *(float2*)&Mp[(long)r * 256 + cc] = make_float2(v0, v1);
            *(float2*)&Mp[(long)(r + 8) * 256 + cc] = make_float2(v2, v3);
        }
    }
}

// av1: M_c += P1 @ X1T'_c  (RMW)
__global__ void __launch_bounds__(256) av1_mma(
    const __nv_bfloat16* __restrict__ P1h, const __nv_bfloat16* __restrict__ P1l,
    const __nv_bfloat16* __restrict__ X1Th, const __nv_bfloat16* __restrict__ X1Tl,
    float* __restrict__ M)
{
    extern __shared__ uint32_t sm[];
    uint32_t smbase = (uint32_t)__cvta_generic_to_shared(sm);
    int tid = threadIdx.x, lane = tid & 31, wid = tid >> 5;
    int wM = wid >> 2, wN = wid & 3, g = lane >> 2, t = lane & 3;
    int bn = blockIdx.z, c = blockIdx.y;
    long po = (long)((bn >> 3) * CC + (bn & 7) * CPH + c) << 16;
    long so = (long)bn << 16;
    int row0 = (blockIdx.x >> 1) << 7;
    int col0 = (blockIdx.x & 1) << 7;
    float acc[4][4][4];
    #pragma unroll
    for (int a = 0; a < 4; ++a)
        #pragma unroll
        for (int b = 0; b < 4; ++b)
            #pragma unroll
            for (int d = 0; d < 4; ++d) acc[a][b][d] = 0.f;

    gemm_run(acc, (const uint4*)(P1h + so) + row0 * 32, (const uint4*)(P1l + so) + row0 * 32,
                  (const uint4*)(X1Th + po) + col0 * 32, (const uint4*)(X1Tl + po) + col0 * 32,
             8, 0, smbase, tid, wM, wN, g, t);

    float* Mp = M + po;
    int rbase = row0 + wM * 64 + g;
    int cbase = col0 + wN * 32 + 2 * t;
    #pragma unroll
    for (int mf = 0; mf < 4; ++mf) {
        int r = rbase + mf * 16;
        #pragma unroll
        for (int nf = 0; nf < 4; ++nf) {
            int cc = cbase + nf * 8;
            float2* p0 = (float2*)&Mp[(long)r * 256 + cc];
            float2* p1 = (float2*)&Mp[(long)(r + 8) * 256 + cc];
            float2 o0 = *p0, o1 = *p1;
            o0.x += acc[mf][nf][0]; o0.y += acc[mf][nf][1];
            o1.x += acc[mf][nf][2]; o1.y += acc[mf][nf][3];
            *p0 = o0; *p1 = o1;
        }
    }
}

// ================= tensor-core 1x1 conv (96x96) =================
#define PKP 50
#define PCH 128
#define PCPB 4
#define PSMEM ((2*96*PKP + 2*PCH*PKP)*4)

__global__ void __launch_bounds__(256) pconv_mma(
    const float* __restrict__ X, const float* __restrict__ Wt, const float* __restrict__ bias,
    float* __restrict__ Y, const float* __restrict__ add1, const float* __restrict__ add2,
    float bscale, __nv_bfloat16* __restrict__ hi, __nv_bfloat16* __restrict__ lo)
{
    extern __shared__ uint32_t psm[];
    uint32_t (*sW)[96][PKP] = (uint32_t(*)[96][PKP])psm;
    uint32_t (*sB)[PCH][PKP] = (uint32_t(*)[PCH][PKP])(psm + 2 * 96 * PKP);
    int tid = threadIdx.x, lane = tid & 31, wid = tid >> 5;
    int g = lane >> 2, t = lane & 3;
    int m0 = (wid >> 2) * 48, n0 = (wid & 3) * 32;
    long bbase = ((long)blockIdx.y * CC) << 16;
    int pos0 = blockIdx.x * (PCH * PCPB);

    for (int pidx = tid; pidx < 96 * 48; pidx += 256) {
        int o = pidx / 48, q = pidx - o * 48;
        float2 wv = *(const float2*)&Wt[o * 96 + 2 * q];
        uint32_t h, l; split2(wv.x, wv.y, h, l);
        sW[0][o][q] = h; sW[1][o][q] = l;
    }

    int bnn = tid & 127, kh = (tid >> 7) * 48;
    float v[48];
    const float* Xp = X + bbase + ((long)kh << 16) + pos0 + bnn;
    #pragma unroll
    for (int k = 0; k < 48; ++k) v[k] = Xp[(long)k << 16];

    for (int ch = 0; ch < PCPB; ++ch) {
        __syncthreads();
        #pragma unroll
        for (int q = 0; q < 24; ++q) {
            uint32_t h, l; split2(v[2 * q], v[2 * q + 1], h, l);
            sB[0][bnn][(kh >> 1) + q] = h;
            sB[1][bnn][(kh >> 1) + q] = l;
        }
        __syncthreads();
        if (ch + 1 < PCPB) {
            const float* Xn = Xp + (ch + 1) * PCH;
            #pragma unroll
            for (int k = 0; k < 48; ++k) v[k] = Xn[(long)k << 16];
        }
        float acc[3][4][4];
        #pragma unroll
        for (int a = 0; a < 3; ++a)
            #pragma unroll
            for (int b = 0; b < 4; ++b)
                #pragma unroll
                for (int d = 0; d < 4; ++d) acc[a][b][d] = 0.f;

        #pragma unroll
        for (int s = 0; s < 6; ++s) {
            int kq = s * 8 + t;
            uint32_t bh[4][2], bl[4][2];
            #pragma unroll
            for (int nf = 0; nf < 4; ++nf) {
                int n = n0 + nf * 8 + g;
                bh[nf][0] = sB[0][n][kq]; bh[nf][1] = sB[0][n][kq + 4];
                bl[nf][0] = sB[1][n][kq]; bl[nf][1] = sB[1][n][kq + 4];
            }
            #pragma unroll
            for (int mf = 0; mf < 3; ++mf) {
                int m = m0 + mf * 16 + g;
                uint32_t ah4[4] = { sW[0][m][kq], sW[0][m + 8][kq], sW[0][m][kq + 4], sW[0][m + 8][kq + 4] };
                uint32_t al4[4] = { sW[1][m][kq], sW[1][m + 8][kq], sW[1][m][kq + 4], sW[1][m + 8][kq + 4] };
                #pragma unroll
                for (int nf = 0; nf < 4; ++nf) {
                    mma_bf16(acc[mf][nf], ah4, bh[nf][0], bh[nf][1]);
                    mma_bf16(acc[mf][nf], al4, bh[nf][0], bh[nf][1]);
                    mma_bf16(acc[mf][nf], ah4, bl[nf][0], bl[nf][1]);
                }
            }
        }
        int posc = pos0 + ch * PCH;
        #pragma unroll
        for (int mf = 0; mf < 3; ++mf) {
            int o = m0 + mf * 16 + g;
            float b0v = bias[o] * bscale, b1v = bias[o + 8] * bscale;
            #pragma unroll
            for (int nf = 0; nf < 4; ++nf) {
                int n = posc + n0 + nf * 8 + 2 * t;
                long i0 = bbase + ((long)o << 16) + n;
                long i1 = bbase + ((long)(o + 8) << 16) + n;
                float r0 = acc[mf][nf][0] + b0v, r1 = acc[mf][nf][1] + b0v;
                float r2 = acc[mf][nf][2] + b1v, r3 = acc[mf][nf][3] + b1v;
                if (add1) {
                    float2 a0 = *(const float2*)&add1[i0], b0 = *(const float2*)&add2[i0];
                    float2 a1 = *(const float2*)&add1[i1], b1 = *(const float2*)&add2[i1];
                    r0 += a0.x + b0.x; r1 += a0.y + b0.y;
                    r2 += a1.x + b1.x; r3 += a1.y + b1.y;
                }
                if (Y) {
                    *(float2*)&Y[i0] = make_float2(r0, r1);
                    *(float2*)&Y[i1] = make_float2(r2, r3);
                }
                if (hi) {
                    uint32_t hh, ll;
                    split2(r0, r1, hh, ll);
                    ((uint32_t*)hi)[i0 >> 1] = hh; ((uint32_t*)lo)[i0 >> 1] = ll;
                    split2(r2, r3, hh, ll);
                    ((uint32_t*)hi)[i1 >> 1] = hh; ((uint32_t*)lo)[i1 >> 1] = ll;
                }
            }
        }
    }
}

// ----------------- softmax (4 rows/block, natural layout, packed split output) -----------------
__global__ void softmax_kernel(
    const float* __restrict__ S, const float* __restrict__ sq, const float* __restrict__ sk,
    __nv_bfloat16* __restrict__ Ph, __nv_bfloat16* __restrict__ Pl)
{
    int bn = blockIdx.y, j2 = threadIdx.x;   // j2: 0..127
    int i0 = blockIdx.x * 4;
    float2 kk = *(const float2*)&sk[bn * 256 + 2 * j2];
    __shared__ float red[4];
    int lane = j2 & 31, warp = j2 >> 5;
    #pragma unroll
    for (int r = 0; r < 4; ++r) {
        int i = i0 + r;
        long base = ((long)bn << 16) + (long)i * 256;
        float2 vv = *(const float2*)&S[base + 2 * j2];
        float qi = sq[bn * 256 + i];
        float v0 = vv.x * qi * kk.x;
        float v1 = vv.y * qi * kk.y;
        float m = fmaxf(v0, v1);
        #pragma unroll
        for (int o = 16; o; o >>= 1) m = fmaxf(m, __shfl_xor_sync(0xffffffffu, m, o));
        if (lane == 0) red[warp] = m;
        __syncthreads();
        m = fmaxf(fmaxf(red[0], red[1]), fmaxf(red[2], red[3]));
        float e0 = expf(v0 - m), e1 = expf(v1 - m);
        float s = e0 + e1;
        #pragma unroll
        for (int o = 16; o; o >>= 1) s += __shfl_xor_sync(0xffffffffu, s, o);
        __syncthreads();
        if (lane == 0) red[warp] = s;
        __syncthreads();
        s = red[0] + red[1] + red[2] + red[3];
        float inv = 1.f / s;
        uint32_t h, l; split2(e0 * inv, e1 * inv, h, l);
        ((uint32_t*)Ph)[(base >> 1) + j2] = h;
        ((uint32_t*)Pl)[(base >> 1) + j2] = l;
        __syncthreads();
    }
}

// ----------------- host launcher -----------------
extern "C" void kernel_launch(void* const* d_in, const int* in_sizes, int n_in,
                              void* d_out, int out_size)
{
    const float* x1    = (const float*)d_in[0];
    const float* x2    = (const float*)d_in[1];
    const float* ln1w  = (const float*)d_in[2];
    const float* ln1b  = (const float*)d_in[3];
    const float* ln2w  = (const float*)d_in[4];
    const float* ln2b  = (const float*)d_in[5];
    const float* projw = (const float*)d_in[6];
    const float* projb = (const float*)d_in[7];
    const float* c11w  = (const float*)d_in[8];
    const float* c11b  = (const float*)d_in[9];
    const float* c12w  = (const float*)d_in[10];
    const float* c12b  = (const float*)d_in[11];
    const float* c21w  = (const float*)d_in[12];
    const float* c21b  = (const float*)d_in[13];
    const float* c22w  = (const float*)d_in[14];
    const float* c22b  = (const float*)d_in[15];

    void* p;
    cudaGetSymbolAddress(&p, g_x1ln); float* x1ln = (float*)p;
    cudaGetSymbolAddress(&p, g_x2ln); float* x2ln = (float*)p;
    cudaGetSymbolAddress(&p, g_tmp);  float* tmp  = (float*)p;
    cudaGetSymbolAddress(&p, g_tmp2); float* tmp2 = (float*)p;
    cudaGetSymbolAddress(&p, g_M);    float* Mbuf = (float*)p;
    cudaGetSymbolAddress(&p, g_S1);   float* S1   = (float*)p;
    cudaGetSymbolAddress(&p, g_S2);   float* S2   = (float*)p;
    cudaGetSymbolAddress(&p, g_scale); float* sc  = (float*)p;
    __nv_bfloat16 *X1h,*X1l,*X2h,*X2l,*O1h,*O1l,*O2h,*O2l;
    __nv_bfloat16 *X1Th,*X1Tl,*X2Th,*X2Tl,*O1Th,*O1Tl,*O2Th,*O2Tl,*P1h,*P1l,*P2h,*P2l;
    cudaGetSymbolAddress(&p, g_X1h);  X1h  = (__nv_bfloat16*)p;
    cudaGetSymbolAddress(&p, g_X1l);  X1l  = (__nv_bfloat16*)p;
    cudaGetSymbolAddress(&p, g_X2h);  X2h  = (__nv_bfloat16*)p;
    cudaGetSymbolAddress(&p, g_X2l);  X2l  = (__nv_bfloat16*)p;
    cudaGetSymbolAddress(&p, g_O1h);  O1h  = (__nv_bfloat16*)p;
    cudaGetSymbolAddress(&p, g_O1l);  O1l  = (__nv_bfloat16*)p;
    cudaGetSymbolAddress(&p, g_O2h);  O2h  = (__nv_bfloat16*)p;
    cudaGetSymbolAddress(&p, g_O2l);  O2l  = (__nv_bfloat16*)p;
    cudaGetSymbolAddress(&p, g_X1Th); X1Th = (__nv_bfloat16*)p;
    cudaGetSymbolAddress(&p, g_X1Tl); X1Tl = (__nv_bfloat16*)p;
    cudaGetSymbolAddress(&p, g_X2Th); X2Th = (__nv_bfloat16*)p;
    cudaGetSymbolAddress(&p, g_X2Tl); X2Tl = (__nv_bfloat16*)p;
    cudaGetSymbolAddress(&p, g_O1Th); O1Th = (__nv_bfloat16*)p;
    cudaGetSymbolAddress(&p, g_O1Tl); O1Tl = (__nv_bfloat16*)p;
    cudaGetSymbolAddress(&p, g_O2Th); O2Th = (__nv_bfloat16*)p;
    cudaGetSymbolAddress(&p, g_O2Tl); O2Tl = (__nv_bfloat16*)p;
    cudaGetSymbolAddress(&p, g_P1h);  P1h  = (__nv_bfloat16*)p;
    cudaGetSymbolAddress(&p, g_P1l);  P1l  = (__nv_bfloat16*)p;
    cudaGetSymbolAddress(&p, g_P2h);  P2h  = (__nv_bfloat16*)p;
    cudaGetSymbolAddress(&p, g_P2l);  P2l  = (__nv_bfloat16*)p;
    const int NS = BNCNT * 256;

    static cudaStream_t sA = nullptr, sB = nullptr, sZ = nullptr;
    static cudaEvent_t eFork, eZ, eL1, eL2, eX2T, eO1T, eO2T, eSc, eP1;
    static int inited = 0;
    if (!inited) {
        cudaStreamCreateWithFlags(&sA, cudaStreamNonBlocking);
        cudaStreamCreateWithFlags(&sB, cudaStreamNonBlocking);
        cudaStreamCreateWithFlags(&sZ, cudaStreamNonBlocking);
        cudaEventCreateWithFlags(&eFork, cudaEventDisableTiming);
        cudaEventCreateWithFlags(&eZ,    cudaEventDisableTiming);
        cudaEventCreateWithFlags(&eL1,   cudaEventDisableTiming);
        cudaEventCreateWithFlags(&eL2,   cudaEventDisableTiming);
        cudaEventCreateWithFlags(&eX2T,  cudaEventDisableTiming);
        cudaEventCreateWithFlags(&eO1T,  cudaEventDisableTiming);
        cudaEventCreateWithFlags(&eO2T,  cudaEventDisableTiming);
        cudaEventCreateWithFlags(&eSc,   cudaEventDisableTiming);
        cudaEventCreateWithFlags(&eP1,   cudaEventDisableTiming);
        cudaFuncSetAttribute(score_mma, cudaFuncAttributeMaxDynamicSharedMemorySize, SMEM_BYTES);
        cudaFuncSetAttribute(av1_mma,  cudaFuncAttributeMaxDynamicSharedMemorySize, SMEM_BYTES);
        cudaFuncSetAttribute(av2_mma,  cudaFuncAttributeMaxDynamicSharedMemorySize, SMEM_BYTES);
        cudaFuncSetAttribute(pconv_mma, cudaFuncAttributeMaxDynamicSharedMemorySize, PSMEM);
        cudaFuncSetAttribute(ln_kernel, cudaFuncAttributeMaxDynamicSharedMemorySize, 98304);
        inited = 1;
    }

    // fork auxiliary streams off the main (capture) stream
    cudaEventRecord(eFork, 0);
    cudaStreamWaitEvent(sA, eFork, 0);
    cudaStreamWaitEvent(sB, eFork, 0);
    cudaStreamWaitEvent(sZ, eFork, 0);

    // sZ: zero norm accumulators
    zero_kernel<<<128, 256, 0, sZ>>>();
    cudaEventRecord(eZ, sZ);

    // main (x1 branch): ln1
    ln_kernel<<<dim3(256, 4), 256, 98304, 0>>>(x1, ln1w, ln1b, x1ln, X1h, X1l);
    cudaEventRecord(eL1, 0);

    // sB (x2 branch): ln2
    ln_kernel<<<dim3(256, 4), 256, 98304, sB>>>(x2, ln2w, ln2b, x2ln, X2h, X2l);
    cudaEventRecord(eL2, sB);

    // sA: the two X transposes (+ norms 0 and 3)
    cudaStreamWaitEvent(sA, eZ, 0);
    cudaStreamWaitEvent(sA, eL1, 0);
    splitT_kernel<<<dim3(32, 384), dim3(32, 8), 0, sA>>>(x1ln, X1Th, X1Tl, 0, -1);
    cudaStreamWaitEvent(sA, eL2, 0);
    splitT_kernel<<<dim3(32, 384), dim3(32, 8), 0, sA>>>(x2ln, X2Th, X2Tl, -1, 3);
    cudaEventRecord(eX2T, sA);

    // main: x1 branch continues (pair-only pconv output)
    dw_kernel<<<dim3(64, 96, 4), 256, 0, 0>>>(x1ln, c11w, c11b, c12w, c12b, tmp);
    pconv_mma<<<dim3(128, 4), 256, PSMEM, 0>>>(tmp, projw, projb, nullptr, nullptr, nullptr, 1.f, O1h, O1l);
    cudaStreamWaitEvent(0, eZ, 0);
    splitT_pair_kernel<<<dim3(32, 384), dim3(32, 8), 0, 0>>>(O1h, O1l, O1Th, O1Tl, 2, -1);  // 2=sq2 row O1
    cudaEventRecord(eO1T, 0);

    // sB: x2 branch continues (pair-only pconv output)
    dw_kernel<<<dim3(64, 96, 4), 256, 0, sB>>>(x2ln, c21w, c21b, c22w, c22b, tmp2);
    pconv_mma<<<dim3(128, 4), 256, PSMEM, sB>>>(tmp2, projw, projb, nullptr, nullptr, nullptr, 1.f, O2h, O2l);
    cudaStreamWaitEvent(sB, eZ, 0);
    splitT_pair_kernel<<<dim3(32, 384), dim3(32, 8), 0, sB>>>(O2h, O2l, O2Th, O2Tl, -1, 1);  // 1=sq1 col O2
    cudaEventRecord(eO2T, sB);

    // sA: scale after all 4 norm contributors
    cudaStreamWaitEvent(sA, eO1T, 0);
    cudaStreamWaitEvent(sA, eO2T, 0);
    scale_kernel<<<128, 256, 0, sA>>>();
    cudaEventRecord(eSc, sA);

    // main: S2 = O1 @ X2T' — compute under sB's remaining memory work
    cudaStreamWaitEvent(0, eX2T, 0);
    score_mma<<<dim3(4, 32), 256, SMEM_BYTES, 0>>>(O1h, O1l, X2Th, X2Tl, S2);

    // sB: S1 = O2T @ X1' then softmax1 -> P1
    cudaStreamWaitEvent(sB, eL1, 0);
    score_mma<<<dim3(4, 32), 256, SMEM_BYTES, sB>>>(O2Th, O2Tl, X1h, X1l, S1);
    cudaStreamWaitEvent(sB, eSc, 0);
    softmax_kernel<<<dim3(64, 32), 128, 0, sB>>>(S1, sc + 1 * NS, sc + 0 * NS, P1h, P1l);
    cudaEventRecord(eP1, sB);

    // main: softmax2 -> P2, then av2 (writes M with residuals)
    cudaStreamWaitEvent(0, eSc, 0);
    softmax_kernel<<<dim3(64, 32), 128, 0, 0>>>(S2, sc + 2 * NS, sc + 3 * NS, P2h, P2l);
    av2_mma<<<dim3(4, 12, 32), 256, SMEM_BYTES, 0>>>(X2h, X2l, P2h, P2l,
                                                     O1Th, O1Tl, O2Th, O2Tl,
                                                     sc + 1 * NS, sc + 2 * NS, Mbuf);

    // main: av1 accumulates P1 @ X1T into M
    cudaStreamWaitEvent(0, eP1, 0);
    av1_mma<<<dim3(4, 12, 32), 256, SMEM_BYTES, 0>>>(P1h, P1l, X1Th, X1Tl, Mbuf);

    // main: final pconv (x2ln ready transitively via eX2T -> eL2)
    pconv_mma<<<dim3(128, 4), 256, PSMEM, 0>>>(Mbuf, projw, projb, (float*)d_out,
                                               x1ln, x2ln, 2.f, nullptr, nullptr);
}

// round 12
// speedup vs baseline: 1.0323x; 1.0323x over previous
#include <cuda_runtime.h>
#include <cuda_bf16.h>
#include <math.h>
#include <stdint.h>

// Problem constants
#define BB 4
#define CC 96
#define HWSZ 65536
#define NHEAD 8
#define CPH 12
#define NTOT (BB*CC*HWSZ)
#define BNCNT (BB*NHEAD)
#define SSZ (BNCNT*HWSZ)

// ----------------- scratch -----------------
__device__ float g_x1ln[NTOT];
__device__ float g_x2ln[NTOT];
__device__ float g_tmp [NTOT];
__device__ float g_tmp2[NTOT];
__device__ float g_out1[NTOT];
__device__ float g_out2[NTOT];
__device__ float g_M   [NTOT];
__device__ float g_S1  [SSZ];
__device__ float g_S2  [SSZ];
__device__ float g_nsq  [4][BNCNT*256];

// bf16 split buffers (hi/lo)
__device__ __nv_bfloat16 g_X1h[NTOT], g_X1l[NTOT];
__device__ __nv_bfloat16 g_X2h[NTOT], g_X2l[NTOT];
__device__ __nv_bfloat16 g_O1h[NTOT], g_O1l[NTOT];
__device__ __nv_bfloat16 g_X1Th[NTOT], g_X1Tl[NTOT];
__device__ __nv_bfloat16 g_X2Th[NTOT], g_X2Tl[NTOT];
__device__ __nv_bfloat16 g_O1Th[NTOT], g_O1Tl[NTOT];
__device__ __nv_bfloat16 g_O2Th[NTOT], g_O2Tl[NTOT];
__device__ __nv_bfloat16 g_P1h[SSZ], g_P1l[SSZ];
__device__ __nv_bfloat16 g_P2h[SSZ], g_P2l[SSZ];

// ----------------- small helpers -----------------
__device__ __forceinline__ void split_store(float v, __nv_bfloat16* hi, __nv_bfloat16* lo, long idx)
{
    __nv_bfloat16 h = __float2bfloat16(v);
    hi[idx] = h;
    lo[idx] = __float2bfloat16(v - __bfloat162float(h));
}

__device__ __forceinline__ void split2(float a, float b, uint32_t& h, uint32_t& l)
{
    __nv_bfloat162 hv = __floats2bfloat162_rn(a, b);
    h = *(uint32_t*)&hv;
    __nv_bfloat162 lv = __floats2bfloat162_rn(a - __bfloat162float(hv.x),
                                              b - __bfloat162float(hv.y));
    l = *(uint32_t*)&lv;
}

__device__ __forceinline__ float2 upk2(uint32_t h, uint32_t l)
{
    __nv_bfloat162 hh = *(__nv_bfloat162*)&h;
    __nv_bfloat162 ll = *(__nv_bfloat162*)&l;
    return make_float2(__bfloat162float(hh.x) + __bfloat162float(ll.x),
                       __bfloat162float(hh.y) + __bfloat162float(ll.y));
}

__device__ __forceinline__ float inv_norm(float nsq)
{
    return 1.f / fmaxf(sqrtf(nsq), 1e-12f);
}

// ----------------- LayerNorm (channel dim), smem-cached, fused bf16 split -----------------
__global__ void ln_kernel(const float* __restrict__ x, const float* __restrict__ w,
                          const float* __restrict__ bsh, float* __restrict__ y,
                          __nv_bfloat16* __restrict__ hi, __nv_bfloat16* __restrict__ lo)
{
    extern __shared__ float lnsm[];   // 96*256 floats
    int tid = threadIdx.x;
    int pos = blockIdx.x * 256 + tid;
    long base = ((long)blockIdx.y * CC) << 16;
    float s = 0.f, ss = 0.f;
    #pragma unroll 8
    for (int c = 0; c < CC; ++c) {
        float v = x[base + ((long)c << 16) + pos];
        lnsm[c * 256 + tid] = v;
        s += v; ss += v * v;
    }
    float mu = s * (1.f / 96.f);
    float var = ss * (1.f / 96.f) - mu * mu;
    float inv = rsqrtf(var + 1e-5f);
    #pragma unroll 8
    for (int c = 0; c < CC; ++c) {
        long id = base + ((long)c << 16) + pos;
        float v = (lnsm[c * 256 + tid] - mu) * inv * w[c] + bsh[c];
        y[id] = v;
        split_store(v, hi, lo, id);
    }
}

// ----------------- transpose+split with cheap fused row/col norms -----------------
__global__ void splitT_kernel(const float* __restrict__ X,
                              __nv_bfloat16* __restrict__ hiT, __nv_bfloat16* __restrict__ loT,
                              int rw, int cw)
{
    __shared__ float ts[64][33];
    __shared__ float colacc[32];
    int p = blockIdx.y;                 // plane 0..383
    int b = p / 96, c = p - b * 96, head = c / 12;
    int nbase = (b * 8 + head) * 256;
    long po = (long)p << 16;
    int h0 = (blockIdx.x >> 3) << 6;
    int w0 = (blockIdx.x & 7) << 5;
    int tx = threadIdx.x, ty = threadIdx.y;
    int tid = ty * 32 + tx;
    if (ty == 0) colacc[tx] = 0.f;
    float cs = 0.f;
    #pragma unroll
    for (int i = 0; i < 8; ++i) {
        int r = ty * 8 + i;
        float v = X[po + (long)(h0 + r) * 256 + w0 + tx];
        ts[r][tx] = v;
        cs += v * v;
    }
    __syncthreads();
    if (cw >= 0) atomicAdd(&colacc[tx], cs);
    if (rw >= 0 && tid < 64) {
        float rs = 0.f;
        #pragma unroll
        for (int q = 0; q < 32; ++q) { float v = ts[tid][q]; rs += v * v; }
        atomicAdd(&g_nsq[rw][nbase + h0 + tid], rs);
    }
    uint32_t* hp = (uint32_t*)hiT;
    uint32_t* lp = (uint32_t*)loT;
    #pragma unroll
    for (int j = 0; j < 4; ++j) {
        int wr = ty * 4 + j;
        float v0 = ts[2 * tx][wr], v1 = ts[2 * tx + 1][wr];
        uint32_t h, l; split2(v0, v1, h, l);
        long oidx = (po + (long)(w0 + wr) * 256 + h0) >> 1;
        hp[oidx + tx] = h;
        lp[oidx + tx] = l;
    }
    if (cw >= 0) {
        __syncthreads();
        if (ty == 0) atomicAdd(&g_nsq[cw][nbase + w0 + tx], colacc[tx]);
    }
}

// ----------------- depthwise (1,7)+(1,11) conv along W, 4 rows/block -----------------
__global__ void dw_kernel(const float* __restrict__ x,
                          const float* __restrict__ w7, const float* __restrict__ b7,
                          const float* __restrict__ w11, const float* __restrict__ b11,
                          float* __restrict__ y)
{
    int hq = blockIdx.x, c = blockIdx.y, b = blockIdx.z;
    long pb = (((long)(b * CC + c)) << 16);
    __shared__ float s[4][272];
    __shared__ float wk[18];
    int tid = threadIdx.x;
    int ty = tid >> 6, tx = tid & 63;
    long rowbase = pb + ((long)(4 * hq + ty) << 8);
    *(float4*)&s[ty][8 + tx * 4] = *(const float4*)&x[rowbase + tx * 4];
    if (tx < 8) { s[ty][tx] = 0.f; s[ty][264 + tx] = 0.f; }
    if (tid < 7) wk[tid] = w7[c * 7 + tid];
    else if (tid < 18) wk[tid] = w11[c * 11 + (tid - 7)];
    __syncthreads();
    float bb = b7[c] + b11[c];
    float o[4];
    #pragma unroll
    for (int u = 0; u < 4; ++u) {
        int wpos = tx * 4 + u;
        float acc = bb;
        #pragma unroll
        for (int k = 0; k < 7; ++k)  acc += s[ty][wpos + 5 + k] * wk[k];
        #pragma unroll
        for (int k = 0; k < 11; ++k) acc += s[ty][wpos + 3 + k] * wk[7 + k];
        o[u] = acc;
    }
    *(float4*)&y[rowbase + tx * 4] = make_float4(o[0], o[1], o[2], o[3]);
}

// ----------------- norm scratch mgmt -----------------
__global__ void zero_kernel()
{
    int i = blockIdx.x * 256 + threadIdx.x;
    if (i < 4 * BNCNT * 256) (&g_nsq[0][0])[i] = 0.f;
}

// ================= mma primitives =================
__device__ __forceinline__ void mma_bf16(float* c, const uint32_t* a, uint32_t b0, uint32_t b1)
{
    asm volatile(
        "mma.sync.aligned.m16n8k16.row.col.f32.bf16.bf16.f32 "
        "{%0,%1,%2,%3},{%4,%5,%6,%7},{%8,%9},{%0,%1,%2,%3};"
        : "+f"(c[0]), "+f"(c[1]), "+f"(c[2]), "+f"(c[3])
        : "r"(a[0]), "r"(a[1]), "r"(a[2]), "r"(a[3]), "r"(b0), "r"(b1));
}

__device__ __forceinline__ void cpa16(uint32_t dst, const void* src)
{
    asm volatile("cp.async.cg.shared.global [%0], [%1], 16;" :: "r"(dst), "l"(src));
}
#define CP_COMMIT() asm volatile("cp.async.commit_group;")
#define CP_WAIT(n)  asm volatile("cp.async.wait_group %0;" :: "n"(n))

// ================= 128x128 bf16-split GEMM core =================
#define KP 20
#define SBUF_OFF (4*128*KP)
#define SMEM_BYTES (8*128*KP*4)

__device__ __forceinline__ void load_stage(int buf, const uint4* ah, const uint4* al,
                                           const uint4* bh, const uint4* bl,
                                           uint32_t smbase, int tid)
{
    #pragma unroll
    for (int i = 0; i < 8; ++i) {
        const int hl  = (i >> 1) & 1;
        const int isB = (i >= 4);
        int r = ((i & 1) << 8) + tid;
        int m = r >> 2, q = r & 3;
        const uint4* src = (isB ? (hl ? bl : bh) : (hl ? al : ah)) + m * 32 + q;
        int w = (((buf * 2 + hl) * 128 + m) * KP + q * 4) + (isB ? SBUF_OFF : 0);
        cpa16(smbase + (w << 2), src);
    }
}

__device__ __forceinline__ void gemm_compute(int buf, float (&acc)[4][4][4],
                                             int wM, int wN, int g, int t)
{
    extern __shared__ uint32_t sm[];
    #pragma unroll
    for (int ks = 0; ks < 2; ++ks) {
        int kq = ks * 8 + t;
        uint32_t bh[4][2], bl[4][2];
        #pragma unroll
        for (int nf = 0; nf < 4; ++nf) {
            int n = wN * 32 + nf * 8 + g;
            const uint32_t* pbh = &sm[SBUF_OFF + ((buf * 2 + 0) * 128 + n) * KP];
            const uint32_t* pbl = &sm[SBUF_OFF + ((buf * 2 + 1) * 128 + n) * KP];
            bh[nf][0] = pbh[kq]; bh[nf][1] = pbh[kq + 4];
            bl[nf][0] = pbl[kq]; bl[nf][1] = pbl[kq + 4];
        }
        #pragma unroll
        for (int mf = 0; mf < 4; ++mf) {
            int rrow = wM * 64 + mf * 16 + g;
            const uint32_t* pah = &sm[((buf * 2 + 0) * 128 + rrow) * KP];
            const uint32_t* pal = &sm[((buf * 2 + 1) * 128 + rrow) * KP];
            uint32_t ah4[4] = { pah[kq], pah[8 * KP + kq], pah[kq + 4], pah[8 * KP + kq + 4] };
            uint32_t al4[4] = { pal[kq], pal[8 * KP + kq], pal[kq + 4], pal[8 * KP + kq + 4] };
            #pragma unroll
            for (int nf = 0; nf < 4; ++nf) {
                mma_bf16(acc[mf][nf], ah4, bh[nf][0], bh[nf][1]);
                mma_bf16(acc[mf][nf], al4, bh[nf][0], bh[nf][1]);
                mma_bf16(acc[mf][nf], ah4, bl[nf][0], bl[nf][1]);
            }
        }
    }
}

__device__ __forceinline__ void gemm_run(float (&acc)[4][4][4],
    const uint4* ah, const uint4* al, const uint4* bh, const uint4* bl,
    int nkt, int ps4, uint32_t smbase, int tid, int wM, int wN, int g, int t)
{
    load_stage(0, ah, al, bh, bl, smbase, tid);
    CP_COMMIT();
    for (int kt = 0; kt < nkt; ++kt) {
        int nx = kt + 1;
        if (nx < nkt) {
            int off = (nx >> 3) * ps4 + (nx & 7) * 4;
            load_stage(nx & 1, ah + off, al + off, bh + off, bl + off, smbase, tid);
            CP_COMMIT();
            CP_WAIT(1);
        } else {
            CP_WAIT(0);
        }
        __syncthreads();
        gemm_compute(kt & 1, acc, wM, wN, g, t);
        __syncthreads();
    }
}

// score: C = A @ B' over 12 planes (K = 3072)
__global__ void __launch_bounds__(256) score_mma(
    const __nv_bfloat16* __restrict__ Ah, const __nv_bfloat16* __restrict__ Al,
    const __nv_bfloat16* __restrict__ Bh, const __nv_bfloat16* __restrict__ Bl,
    float* __restrict__ C)
{
    extern __shared__ uint32_t sm[];
    uint32_t smbase = (uint32_t)__cvta_generic_to_shared(sm);
    int tid = threadIdx.x, lane = tid & 31, wid = tid >> 5;
    int wM = wid >> 2, wN = wid & 3, g = lane >> 2, t = lane & 3;
    int bn = blockIdx.y;
    long po = (long)((bn >> 3) * CC + (bn & 7) * CPH) << 16;
    int row0 = (blockIdx.x >> 1) << 7;
    int col0 = (blockIdx.x & 1) << 7;
    const uint4* ah = (const uint4*)(Ah + po) + row0 * 32;
    const uint4* al = (const uint4*)(Al + po) + row0 * 32;
    const uint4* bh = (const uint4*)(Bh + po) + col0 * 32;
    const uint4* bl = (const uint4*)(Bl + po) + col0 * 32;
    float acc[4][4][4];
    #pragma unroll
    for (int a = 0; a < 4; ++a)
        #pragma unroll
        for (int b = 0; b < 4; ++b)
            #pragma unroll
            for (int d = 0; d < 4; ++d) acc[a][b][d] = 0.f;

    gemm_run(acc, ah, al, bh, bl, 96, 8192, smbase, tid, wM, wN, g, t);

    float* Cp = C + ((long)bn << 16);
    int rbase = row0 + wM * 64 + g;
    int cbase = col0 + wN * 32 + 2 * t;
    #pragma unroll
    for (int mf = 0; mf < 4; ++mf) {
        int r = rbase + mf * 16;
        #pragma unroll
        for (int nf = 0; nf < 4; ++nf) {
            int cc = cbase + nf * 8;
            *(float2*)&Cp[(long)r * 256 + cc] = make_float2(acc[mf][nf][0], acc[mf][nf][1]);
            *(float2*)&Cp[(long)(r + 8) * 256 + cc] = make_float2(acc[mf][nf][2], acc[mf][nf][3]);
        }
    }
}

// av2: M_c = X2_c @ P2' + residual(O2T*s1 + O1T*s2); s from nsq (inline rsqrt)
__global__ void __launch_bounds__(256) av2_mma(
    const __nv_bfloat16* __restrict__ X2h, const __nv_bfloat16* __restrict__ X2l,
    const __nv_bfloat16* __restrict__ P2h, const __nv_bfloat16* __restrict__ P2l,
    const __nv_bfloat16* __restrict__ O1Th, const __nv_bfloat16* __restrict__ O1Tl,
    const __nv_bfloat16* __restrict__ O2Th, const __nv_bfloat16* __restrict__ O2Tl,
    const float* __restrict__ n1, const float* __restrict__ n2,
    float* __restrict__ M)
{
    extern __shared__ uint32_t sm[];
    uint32_t smbase = (uint32_t)__cvta_generic_to_shared(sm);
    int tid = threadIdx.x, lane = tid & 31, wid = tid >> 5;
    int wM = wid >> 2, wN = wid & 3, g = lane >> 2, t = lane & 3;
    int bn = blockIdx.z, c = blockIdx.y;
    long po = (long)((bn >> 3) * CC + (bn & 7) * CPH + c) << 16;
    long so = (long)bn << 16;
    int row0 = (blockIdx.x >> 1) << 7;
    int col0 = (blockIdx.x & 1) << 7;
    float acc[4][4][4];
    #pragma unroll
    for (int a = 0; a < 4; ++a)
        #pragma unroll
        for (int b = 0; b < 4; ++b)
            #pragma unroll
            for (int d = 0; d < 4; ++d) acc[a][b][d] = 0.f;

    gemm_run(acc, (const uint4*)(X2h + po) + row0 * 32, (const uint4*)(X2l + po) + row0 * 32,
                  (const uint4*)(P2h + so) + col0 * 32, (const uint4*)(P2l + so) + col0 * 32,
             8, 0, smbase, tid, wM, wN, g, t);

    const uint32_t* pO1h = (const uint32_t*)(O1Th + po);
    const uint32_t* pO1l = (const uint32_t*)(O1Tl + po);
    const uint32_t* pO2h = (const uint32_t*)(O2Th + po);
    const uint32_t* pO2l = (const uint32_t*)(O2Tl + po);
    const float* n1p = n1 + bn * 256;
    const float* n2p = n2 + bn * 256;
    float* Mp = M + po;
    int rbase = row0 + wM * 64 + g;
    int cbase = col0 + wN * 32 + 2 * t;
    #pragma unroll
    for (int mf = 0; mf < 4; ++mf) {
        int r = rbase + mf * 16;
        float s1a = inv_norm(n1p[r]), s1b = inv_norm(n1p[r + 8]);
        #pragma unroll
        for (int nf = 0; nf < 4; ++nf) {
            int cc = cbase + nf * 8;
            float s2a = inv_norm(n2p[cc]), s2b = inv_norm(n2p[cc + 1]);
            long q0 = ((long)r * 256 + cc) >> 1;
            long q1 = ((long)(r + 8) * 256 + cc) >> 1;
            float2 o1a = upk2(pO1h[q0], pO1l[q0]);
            float2 o2a = upk2(pO2h[q0], pO2l[q0]);
            float2 o1b = upk2(pO1h[q1], pO1l[q1]);
            float2 o2b = upk2(pO2h[q1], pO2l[q1]);
            float v0 = acc[mf][nf][0] + o2a.x * s1a + o1a.x * s2a;
            float v1 = acc[mf][nf][1] + o2a.y * s1a + o1a.y * s2b;
            float v2 = acc[mf][nf][2] + o2b.x * s1b + o1b.x * s2a;
            float v3 = acc[mf][nf][3] + o2b.y * s1b + o1b.y * s2b;
            *(float2*)&Mp[(long)r * 256 + cc] = make_float2(v0, v1);
            *(float2*)&Mp[(long)(r + 8) * 256 + cc] = make_float2(v2, v3);
        }
    }
}

// av1: M_c += P1 @ X1T'_c  (RMW)
__global__ void __launch_bounds__(256) av1_mma(
    const __nv_bfloat16* __restrict__ P1h, const __nv_bfloat16* __restrict__ P1l,
    const __nv_bfloat16* __restrict__ X1Th, const __nv_bfloat16* __restrict__ X1Tl,
    float* __restrict__ M)
{
    extern __shared__ uint32_t sm[];
    uint32_t smbase = (uint32_t)__cvta_generic_to_shared(sm);
    int tid = threadIdx.x, lane = tid & 31, wid = tid >> 5;
    int wM = wid >> 2, wN = wid & 3, g = lane >> 2, t = lane & 3;
    int bn = blockIdx.z, c = blockIdx.y;
    long po = (long)((bn >> 3) * CC + (bn & 7) * CPH + c) << 16;
    long so = (long)bn << 16;
    int row0 = (blockIdx.x >> 1) << 7;
    int col0 = (blockIdx.x & 1) << 7;
    float acc[4][4][4];
    #pragma unroll
    for (int a = 0; a < 4; ++a)
        #pragma unroll
        for (int b = 0; b < 4; ++b)
            #pragma unroll
            for (int d = 0; d < 4; ++d) acc[a][b][d] = 0.f;

    gemm_run(acc, (const uint4*)(P1h + so) + row0 * 32, (const uint4*)(P1l + so) + row0 * 32,
                  (const uint4*)(X1Th + po) + col0 * 32, (const uint4*)(X1Tl + po) + col0 * 32,
             8, 0, smbase, tid, wM, wN, g, t);

    float* Mp = M + po;
    int rbase = row0 + wM * 64 + g;
    int cbase = col0 + wN * 32 + 2 * t;
    #pragma unroll
    for (int mf = 0; mf < 4; ++mf) {
        int r = rbase + mf * 16;
        #pragma unroll
        for (int nf = 0; nf < 4; ++nf) {
            int cc = cbase + nf * 8;
            float2* p0 = (float2*)&Mp[(long)r * 256 + cc];
            float2* p1 = (float2*)&Mp[(long)(r + 8) * 256 + cc];
            float2 o0 = *p0, o1 = *p1;
            o0.x += acc[mf][nf][0]; o0.y += acc[mf][nf][1];
            o1.x += acc[mf][nf][2]; o1.y += acc[mf][nf][3];
            *p0 = o0; *p1 = o1;
        }
    }
}

// ================= tensor-core 1x1 conv (96x96) =================
#define PKP 50
#define PCH 128
#define PCPB 4
#define PSMEM ((2*96*PKP + 2*PCH*PKP)*4)

__global__ void __launch_bounds__(256) pconv_mma(
    const float* __restrict__ X, const float* __restrict__ Wt, const float* __restrict__ bias,
    float* __restrict__ Y, const float* __restrict__ add1, const float* __restrict__ add2,
    float bscale, __nv_bfloat16* __restrict__ hi, __nv_bfloat16* __restrict__ lo)
{
    extern __shared__ uint32_t psm[];
    uint32_t (*sW)[96][PKP] = (uint32_t(*)[96][PKP])psm;
    uint32_t (*sB)[PCH][PKP] = (uint32_t(*)[PCH][PKP])(psm + 2 * 96 * PKP);
    int tid = threadIdx.x, lane = tid & 31, wid = tid >> 5;
    int g = lane >> 2, t = lane & 3;
    int m0 = (wid >> 2) * 48, n0 = (wid & 3) * 32;
    long bbase = ((long)blockIdx.y * CC) << 16;
    int pos0 = blockIdx.x * (PCH * PCPB);

    for (int pidx = tid; pidx < 96 * 48; pidx += 256) {
        int o = pidx / 48, q = pidx - o * 48;
        float2 wv = *(const float2*)&Wt[o * 96 + 2 * q];
        uint32_t h, l; split2(wv.x, wv.y, h, l);
        sW[0][o][q] = h; sW[1][o][q] = l;
    }

    int bnn = tid & 127, kh = (tid >> 7) * 48;
    float v[48];
    const float* Xp = X + bbase + ((long)kh << 16) + pos0 + bnn;
    #pragma unroll
    for (int k = 0; k < 48; ++k) v[k] = Xp[(long)k << 16];

    for (int ch = 0; ch < PCPB; ++ch) {
        __syncthreads();
        #pragma unroll
        for (int q = 0; q < 24; ++q) {
            uint32_t h, l; split2(v[2 * q], v[2 * q + 1], h, l);
            sB[0][bnn][(kh >> 1) + q] = h;
            sB[1][bnn][(kh >> 1) + q] = l;
        }
        __syncthreads();
        if (ch + 1 < PCPB) {
            const float* Xn = Xp + (ch + 1) * PCH;
            #pragma unroll
            for (int k = 0; k < 48; ++k) v[k] = Xn[(long)k << 16];
        }
        float acc[3][4][4];
        #pragma unroll
        for (int a = 0; a < 3; ++a)
            #pragma unroll
            for (int b = 0; b < 4; ++b)
                #pragma unroll
                for (int d = 0; d < 4; ++d) acc[a][b][d] = 0.f;

        #pragma unroll
        for (int s = 0; s < 6; ++s) {
            int kq = s * 8 + t;
            uint32_t bh[4][2], bl[4][2];
            #pragma unroll
            for (int nf = 0; nf < 4; ++nf) {
                int n = n0 + nf * 8 + g;
                bh[nf][0] = sB[0][n][kq]; bh[nf][1] = sB[0][n][kq + 4];
                bl[nf][0] = sB[1][n][kq]; bl[nf][1] = sB[1][n][kq + 4];
            }
            #pragma unroll
            for (int mf = 0; mf < 3; ++mf) {
                int m = m0 + mf * 16 + g;
                uint32_t ah4[4] = { sW[0][m][kq], sW[0][m + 8][kq], sW[0][m][kq + 4], sW[0][m + 8][kq + 4] };
                uint32_t al4[4] = { sW[1][m][kq], sW[1][m + 8][kq], sW[1][m][kq + 4], sW[1][m + 8][kq + 4] };
                #pragma unroll
                for (int nf = 0; nf < 4; ++nf) {
                    mma_bf16(acc[mf][nf], ah4, bh[nf][0], bh[nf][1]);
                    mma_bf16(acc[mf][nf], al4, bh[nf][0], bh[nf][1]);
                    mma_bf16(acc[mf][nf], ah4, bl[nf][0], bl[nf][1]);
                }
            }
        }
        int posc = pos0 + ch * PCH;
        #pragma unroll
        for (int mf = 0; mf < 3; ++mf) {
            int o = m0 + mf * 16 + g;
            float b0v = bias[o] * bscale, b1v = bias[o + 8] * bscale;
            #pragma unroll
            for (int nf = 0; nf < 4; ++nf) {
                int n = posc + n0 + nf * 8 + 2 * t;
                long i0 = bbase + ((long)o << 16) + n;
                long i1 = bbase + ((long)(o + 8) << 16) + n;
                float r0 = acc[mf][nf][0] + b0v, r1 = acc[mf][nf][1] + b0v;
                float r2 = acc[mf][nf][2] + b1v, r3 = acc[mf][nf][3] + b1v;
                if (add1) {
                    float2 a0 = *(const float2*)&add1[i0], b0 = *(const float2*)&add2[i0];
                    float2 a1 = *(const float2*)&add1[i1], b1 = *(const float2*)&add2[i1];
                    r0 += a0.x + b0.x; r1 += a0.y + b0.y;
                    r2 += a1.x + b1.x; r3 += a1.y + b1.y;
                }
                *(float2*)&Y[i0] = make_float2(r0, r1);
                *(float2*)&Y[i1] = make_float2(r2, r3);
                if (hi) {
                    uint32_t hh, ll;
                    split2(r0, r1, hh, ll);
                    ((uint32_t*)hi)[i0 >> 1] = hh; ((uint32_t*)lo)[i0 >> 1] = ll;
                    split2(r2, r3, hh, ll);
                    ((uint32_t*)hi)[i1 >> 1] = hh; ((uint32_t*)lo)[i1 >> 1] = ll;
                }
            }
        }
    }
}

// ----------------- softmax (4 rows/block, inline inverse-norm from nsq) -----------------
__global__ void softmax_kernel(
    const float* __restrict__ S, const float* __restrict__ nq, const float* __restrict__ nk,
    __nv_bfloat16* __restrict__ Ph, __nv_bfloat16* __restrict__ Pl)
{
    int bn = blockIdx.y, j2 = threadIdx.x;   // j2: 0..127
    int i0 = blockIdx.x * 4;
    float2 nkk = *(const float2*)&nk[bn * 256 + 2 * j2];
    float2 kk = make_float2(inv_norm(nkk.x), inv_norm(nkk.y));
    __shared__ float red[4];
    int lane = j2 & 31, warp = j2 >> 5;
    #pragma unroll
    for (int r = 0; r < 4; ++r) {
        int i = i0 + r;
        long base = ((long)bn << 16) + (long)i * 256;
        float2 vv = *(const float2*)&S[base + 2 * j2];
        float qi = inv_norm(nq[bn * 256 + i]);
        float v0 = vv.x * qi * kk.x;
        float v1 = vv.y * qi * kk.y;
        float m = fmaxf(v0, v1);
        #pragma unroll
        for (int o = 16; o; o >>= 1) m = fmaxf(m, __shfl_xor_sync(0xffffffffu, m, o));
        if (lane == 0) red[warp] = m;
        __syncthreads();
        m = fmaxf(fmaxf(red[0], red[1]), fmaxf(red[2], red[3]));
        float e0 = expf(v0 - m), e1 = expf(v1 - m);
        float s = e0 + e1;
        #pragma unroll
        for (int o = 16; o; o >>= 1) s += __shfl_xor_sync(0xffffffffu, s, o);
        __syncthreads();
        if (lane == 0) red[warp] = s;
        __syncthreads();
        s = red[0] + red[1] + red[2] + red[3];
        float inv = 1.f / s;
        uint32_t h, l; split2(e0 * inv, e1 * inv, h, l);
        ((uint32_t*)Ph)[(base >> 1) + j2] = h;
        ((uint32_t*)Pl)[(base >> 1) + j2] = l;
        __syncthreads();
    }
}

// ----------------- host launcher -----------------
extern "C" void kernel_launch(void* const* d_in, const int* in_sizes, int n_in,
                              void* d_out, int out_size)
{
    const float* x1    = (const float*)d_in[0];
    const float* x2    = (const float*)d_in[1];
    const float* ln1w  = (const float*)d_in[2];
    const float* ln1b  = (const float*)d_in[3];
    const float* ln2w  = (const float*)d_in[4];
    const float* ln2b  = (const float*)d_in[5];
    const float* projw = (const float*)d_in[6];
    const float* projb = (const float*)d_in[7];
    const float* c11w  = (const float*)d_in[8];
    const float* c11b  = (const float*)d_in[9];
    const float* c12w  = (const float*)d_in[10];
    const float* c12b  = (const float*)d_in[11];
    const float* c21w  = (const float*)d_in[12];
    const float* c21b  = (const float*)d_in[13];
    const float* c22w  = (const float*)d_in[14];
    const float* c22b  = (const float*)d_in[15];

    void* p;
    cudaGetSymbolAddress(&p, g_x1ln); float* x1ln = (float*)p;
    cudaGetSymbolAddress(&p, g_x2ln); float* x2ln = (float*)p;
    cudaGetSymbolAddress(&p, g_tmp);  float* tmp  = (float*)p;
    cudaGetSymbolAddress(&p, g_tmp2); float* tmp2 = (float*)p;
    cudaGetSymbolAddress(&p, g_out1); float* out1 = (float*)p;
    cudaGetSymbolAddress(&p, g_out2); float* out2 = (float*)p;
    cudaGetSymbolAddress(&p, g_M);    float* Mbuf = (float*)p;
    cudaGetSymbolAddress(&p, g_S1);   float* S1   = (float*)p;
    cudaGetSymbolAddress(&p, g_S2);   float* S2   = (float*)p;
    cudaGetSymbolAddress(&p, g_nsq);  float* nsq  = (float*)p;
    __nv_bfloat16 *X1h,*X1l,*X2h,*X2l,*O1h,*O1l,*X1Th,*X1Tl,*X2Th,*X2Tl,*O1Th,*O1Tl,*O2Th,*O2Tl,*P1h,*P1l,*P2h,*P2l;
    cudaGetSymbolAddress(&p, g_X1h);  X1h  = (__nv_bfloat16*)p;
    cudaGetSymbolAddress(&p, g_X1l);  X1l  = (__nv_bfloat16*)p;
    cudaGetSymbolAddress(&p, g_X2h);  X2h  = (__nv_bfloat16*)p;
    cudaGetSymbolAddress(&p, g_X2l);  X2l  = (__nv_bfloat16*)p;
    cudaGetSymbolAddress(&p, g_O1h);  O1h  = (__nv_bfloat16*)p;
    cudaGetSymbolAddress(&p, g_O1l);  O1l  = (__nv_bfloat16*)p;
    cudaGetSymbolAddress(&p, g_X1Th); X1Th = (__nv_bfloat16*)p;
    cudaGetSymbolAddress(&p, g_X1Tl); X1Tl = (__nv_bfloat16*)p;
    cudaGetSymbolAddress(&p, g_X2Th); X2Th = (__nv_bfloat16*)p;
    cudaGetSymbolAddress(&p, g_X2Tl); X2Tl = (__nv_bfloat16*)p;
    cudaGetSymbolAddress(&p, g_O1Th); O1Th = (__nv_bfloat16*)p;
    cudaGetSymbolAddress(&p, g_O1Tl); O1Tl = (__nv_bfloat16*)p;
    cudaGetSymbolAddress(&p, g_O2Th); O2Th = (__nv_bfloat16*)p;
    cudaGetSymbolAddress(&p, g_O2Tl); O2Tl = (__nv_bfloat16*)p;
    cudaGetSymbolAddress(&p, g_P1h);  P1h  = (__nv_bfloat16*)p;
    cudaGetSymbolAddress(&p, g_P1l);  P1l  = (__nv_bfloat16*)p;
    cudaGetSymbolAddress(&p, g_P2h);  P2h  = (__nv_bfloat16*)p;
    cudaGetSymbolAddress(&p, g_P2l);  P2l  = (__nv_bfloat16*)p;
    const int NS = BNCNT * 256;

    static cudaStream_t sA = nullptr, sB = nullptr, sZ = nullptr;
    static cudaEvent_t eFork, eZ, eL1, eL2, eX2T, eO1T, eO2T, eP1;
    static int inited = 0;
    if (!inited) {
        cudaStreamCreateWithFlags(&sA, cudaStreamNonBlocking);
        cudaStreamCreateWithFlags(&sB, cudaStreamNonBlocking);
        cudaStreamCreateWithFlags(&sZ, cudaStreamNonBlocking);
        cudaEventCreateWithFlags(&eFork, cudaEventDisableTiming);
        cudaEventCreateWithFlags(&eZ,    cudaEventDisableTiming);
        cudaEventCreateWithFlags(&eL1,   cudaEventDisableTiming);
        cudaEventCreateWithFlags(&eL2,   cudaEventDisableTiming);
        cudaEventCreateWithFlags(&eX2T,  cudaEventDisableTiming);
        cudaEventCreateWithFlags(&eO1T,  cudaEventDisableTiming);
        cudaEventCreateWithFlags(&eO2T,  cudaEventDisableTiming);
        cudaEventCreateWithFlags(&eP1,   cudaEventDisableTiming);
        cudaFuncSetAttribute(score_mma, cudaFuncAttributeMaxDynamicSharedMemorySize, SMEM_BYTES);
        cudaFuncSetAttribute(av1_mma,  cudaFuncAttributeMaxDynamicSharedMemorySize, SMEM_BYTES);
        cudaFuncSetAttribute(av2_mma,  cudaFuncAttributeMaxDynamicSharedMemorySize, SMEM_BYTES);
        cudaFuncSetAttribute(pconv_mma, cudaFuncAttributeMaxDynamicSharedMemorySize, PSMEM);
        cudaFuncSetAttribute(ln_kernel, cudaFuncAttributeMaxDynamicSharedMemorySize, 98304);
        inited = 1;
    }

    // fork auxiliary streams off the main (capture) stream
    cudaEventRecord(eFork, 0);
    cudaStreamWaitEvent(sA, eFork, 0);
    cudaStreamWaitEvent(sB, eFork, 0);
    cudaStreamWaitEvent(sZ, eFork, 0);

    // sZ: zero norm accumulators
    zero_kernel<<<128, 256, 0, sZ>>>();
    cudaEventRecord(eZ, sZ);

    // main (x1 branch): ln1
    ln_kernel<<<dim3(256, 4), 256, 98304, 0>>>(x1, ln1w, ln1b, x1ln, X1h, X1l);
    cudaEventRecord(eL1, 0);

    // sB (x2 branch): ln2
    ln_kernel<<<dim3(256, 4), 256, 98304, sB>>>(x2, ln2w, ln2b, x2ln, X2h, X2l);
    cudaEventRecord(eL2, sB);

    // sA: the two X transposes (+ norms 0 and 3)
    cudaStreamWaitEvent(sA, eZ, 0);
    cudaStreamWaitEvent(sA, eL1, 0);
    splitT_kernel<<<dim3(32, 384), dim3(32, 8), 0, sA>>>(x1ln, X1Th, X1Tl, 0, -1);
    cudaStreamWaitEvent(sA, eL2, 0);
    splitT_kernel<<<dim3(32, 384), dim3(32, 8), 0, sA>>>(x2ln, X2Th, X2Tl, -1, 3);
    cudaEventRecord(eX2T, sA);

    // main: x1 branch continues
    dw_kernel<<<dim3(64, 96, 4), 256, 0, 0>>>(x1ln, c11w, c11b, c12w, c12b, tmp);
    pconv_mma<<<dim3(128, 4), 256, PSMEM, 0>>>(tmp, projw, projb, out1, nullptr, nullptr, 1.f, O1h, O1l);
    cudaStreamWaitEvent(0, eZ, 0);
    splitT_kernel<<<dim3(32, 384), dim3(32, 8), 0, 0>>>(out1, O1Th, O1Tl, 2, -1);   // 2=sq2 row out1
    cudaEventRecord(eO1T, 0);

    // sB: x2 branch continues
    dw_kernel<<<dim3(64, 96, 4), 256, 0, sB>>>(x2ln, c21w, c21b, c22w, c22b, tmp2);
    pconv_mma<<<dim3(128, 4), 256, PSMEM, sB>>>(tmp2, projw, projb, out2, nullptr, nullptr, 1.f, nullptr, nullptr);
    cudaStreamWaitEvent(sB, eZ, 0);
    splitT_kernel<<<dim3(32, 384), dim3(32, 8), 0, sB>>>(out2, O2Th, O2Tl, -1, 1);  // 1=sq1 col out2
    cudaEventRecord(eO2T, sB);

    // main: S2 = O1 @ X2T' — compute under sB's remaining memory work
    cudaStreamWaitEvent(0, eX2T, 0);
    score_mma<<<dim3(4, 32), 256, SMEM_BYTES, 0>>>(O1h, O1l, X2Th, X2Tl, S2);

    // sB: S1 = O2T @ X1' then softmax1 -> P1 (needs nsq0 from sA [eX2T], nsq1 in-stream)
    cudaStreamWaitEvent(sB, eL1, 0);
    score_mma<<<dim3(4, 32), 256, SMEM_BYTES, sB>>>(O2Th, O2Tl, X1h, X1l, S1);
    cudaStreamWaitEvent(sB, eX2T, 0);
    softmax_kernel<<<dim3(64, 32), 128, 0, sB>>>(S1, nsq + 1 * NS, nsq + 0 * NS, P1h, P1l);
    cudaEventRecord(eP1, sB);

    // main: softmax2 -> P2 (nsq2 in-stream, nsq3 via eX2T already waited), then av2
    softmax_kernel<<<dim3(64, 32), 128, 0, 0>>>(S2, nsq + 2 * NS, nsq + 3 * NS, P2h, P2l);
    cudaStreamWaitEvent(0, eO2T, 0);   // av2 needs O2T data + nsq1
    av2_mma<<<dim3(4, 12, 32), 256, SMEM_BYTES, 0>>>(X2h, X2l, P2h, P2l,
                                                     O1Th, O1Tl, O2Th, O2Tl,
                                                     nsq + 1 * NS, nsq + 2 * NS, Mbuf);

    // main: av1 accumulates P1 @ X1T into M
    cudaStreamWaitEvent(0, eP1, 0);
    av1_mma<<<dim3(4, 12, 32), 256, SMEM_BYTES, 0>>>(P1h, P1l, X1Th, X1Tl, Mbuf);

    // main: final pconv (x2ln ready transitively via eX2T -> eL2)
    pconv_mma<<<dim3(128, 4), 256, PSMEM, 0>>>(Mbuf, projw, projb, (float*)d_out,
                                               x1ln, x2ln, 2.f, nullptr, nullptr);
}

// round 13
// speedup vs baseline: 1.0489x; 1.0161x over previous
#include <cuda_runtime.h>
#include <cuda_bf16.h>
#include <math.h>
#include <stdint.h>

// Problem constants
#define BB 4
#define CC 96
#define HWSZ 65536
#define NHEAD 8
#define CPH 12
#define NTOT (BB*CC*HWSZ)
#define BNCNT (BB*NHEAD)
#define SSZ (BNCNT*HWSZ)

// ----------------- scratch -----------------
__device__ float g_x1ln[NTOT];
__device__ float g_x2ln[NTOT];
__device__ float g_tmp [NTOT];
__device__ float g_tmp2[NTOT];
__device__ float g_out1[NTOT];
__device__ float g_out2[NTOT];
__device__ float g_M   [NTOT];
__device__ float g_S1  [SSZ];
__device__ float g_S2  [SSZ];
__device__ float g_nsq  [4][BNCNT*256];
__device__ float g_scale[4][BNCNT*256];

// bf16 split buffers (hi/lo)
__device__ __nv_bfloat16 g_X1h[NTOT], g_X1l[NTOT];
__device__ __nv_bfloat16 g_X2h[NTOT], g_X2l[NTOT];
__device__ __nv_bfloat16 g_O1h[NTOT], g_O1l[NTOT];
__device__ __nv_bfloat16 g_X1Th[NTOT], g_X1Tl[NTOT];
__device__ __nv_bfloat16 g_X2Th[NTOT], g_X2Tl[NTOT];
__device__ __nv_bfloat16 g_O1Th[NTOT], g_O1Tl[NTOT];
__device__ __nv_bfloat16 g_O2Th[NTOT], g_O2Tl[NTOT];
__device__ __nv_bfloat16 g_P1h[SSZ], g_P1l[SSZ];
__device__ __nv_bfloat16 g_P2h[SSZ], g_P2l[SSZ];

// ----------------- small helpers -----------------
__device__ __forceinline__ void split_store(float v, __nv_bfloat16* hi, __nv_bfloat16* lo, long idx)
{
    __nv_bfloat16 h = __float2bfloat16(v);
    hi[idx] = h;
    lo[idx] = __float2bfloat16(v - __bfloat162float(h));
}

__device__ __forceinline__ void split2(float a, float b, uint32_t& h, uint32_t& l)
{
    __nv_bfloat162 hv = __floats2bfloat162_rn(a, b);
    h = *(uint32_t*)&hv;
    __nv_bfloat162 lv = __floats2bfloat162_rn(a - __bfloat162float(hv.x),
                                              b - __bfloat162float(hv.y));
    l = *(uint32_t*)&lv;
}

__device__ __forceinline__ float2 upk2(uint32_t h, uint32_t l)
{
    __nv_bfloat162 hh = *(__nv_bfloat162*)&h;
    __nv_bfloat162 ll = *(__nv_bfloat162*)&l;
    return make_float2(__bfloat162float(hh.x) + __bfloat162float(ll.x),
                       __bfloat162float(hh.y) + __bfloat162float(ll.y));
}

// ----------------- LayerNorm (channel dim), smem-cached, fused bf16 split -----------------
__global__ void ln_kernel(const float* __restrict__ x, const float* __restrict__ w,
                          const float* __restrict__ bsh, float* __restrict__ y,
                          __nv_bfloat16* __restrict__ hi, __nv_bfloat16* __restrict__ lo)
{
    extern __shared__ float lnsm[];   // 96*256 floats
    int tid = threadIdx.x;
    int pos = blockIdx.x * 256 + tid;
    long base = ((long)blockIdx.y * CC) << 16;
    float s = 0.f, ss = 0.f;
    #pragma unroll 8
    for (int c = 0; c < CC; ++c) {
        float v = x[base + ((long)c << 16) + pos];
        lnsm[c * 256 + tid] = v;
        s += v; ss += v * v;
    }
    float mu = s * (1.f / 96.f);
    float var = ss * (1.f / 96.f) - mu * mu;
    float inv = rsqrtf(var + 1e-5f);
    #pragma unroll 8
    for (int c = 0; c < CC; ++c) {
        long id = base + ((long)c << 16) + pos;
        float v = (lnsm[c * 256 + tid] - mu) * inv * w[c] + bsh[c];
        y[id] = v;
        split_store(v, hi, lo, id);
    }
}

// ----------------- transpose+split with cheap fused row/col norms -----------------
__global__ void splitT_kernel(const float* __restrict__ X,
                              __nv_bfloat16* __restrict__ hiT, __nv_bfloat16* __restrict__ loT,
                              int rw, int cw)
{
    __shared__ float ts[64][33];
    __shared__ float colacc[32];
    int p = blockIdx.y;                 // plane 0..383
    int b = p / 96, c = p - b * 96, head = c / 12;
    int nbase = (b * 8 + head) * 256;
    long po = (long)p << 16;
    int h0 = (blockIdx.x >> 3) << 6;
    int w0 = (blockIdx.x & 7) << 5;
    int tx = threadIdx.x, ty = threadIdx.y;
    int tid = ty * 32 + tx;
    if (ty == 0) colacc[tx] = 0.f;
    float cs = 0.f;
    #pragma unroll
    for (int i = 0; i < 8; ++i) {
        int r = ty * 8 + i;
        float v = X[po + (long)(h0 + r) * 256 + w0 + tx];
        ts[r][tx] = v;
        cs += v * v;
    }
    __syncthreads();
    if (cw >= 0) atomicAdd(&colacc[tx], cs);
    if (rw >= 0 && tid < 64) {
        float rs = 0.f;
        #pragma unroll
        for (int q = 0; q < 32; ++q) { float v = ts[tid][q]; rs += v * v; }
        atomicAdd(&g_nsq[rw][nbase + h0 + tid], rs);
    }
    uint32_t* hp = (uint32_t*)hiT;
    uint32_t* lp = (uint32_t*)loT;
    #pragma unroll
    for (int j = 0; j < 4; ++j) {
        int wr = ty * 4 + j;
        float v0 = ts[2 * tx][wr], v1 = ts[2 * tx + 1][wr];
        uint32_t h, l; split2(v0, v1, h, l);
        long oidx = (po + (long)(w0 + wr) * 256 + h0) >> 1;
        hp[oidx + tx] = h;
        lp[oidx + tx] = l;
    }
    if (cw >= 0) {
        __syncthreads();
        if (ty == 0) atomicAdd(&g_nsq[cw][nbase + w0 + tx], colacc[tx]);
    }
}

// ----------------- depthwise (1,7)+(1,11) conv along W, 4 rows/block -----------------
__global__ void dw_kernel(const float* __restrict__ x,
                          const float* __restrict__ w7, const float* __restrict__ b7,
                          const float* __restrict__ w11, const float* __restrict__ b11,
                          float* __restrict__ y)
{
    int hq = blockIdx.x, c = blockIdx.y, b = blockIdx.z;
    long pb = (((long)(b * CC + c)) << 16);
    __shared__ float s[4][272];
    __shared__ float wk[18];
    int tid = threadIdx.x;
    int ty = tid >> 6, tx = tid & 63;
    long rowbase = pb + ((long)(4 * hq + ty) << 8);
    *(float4*)&s[ty][8 + tx * 4] = *(const float4*)&x[rowbase + tx * 4];
    if (tx < 8) { s[ty][tx] = 0.f; s[ty][264 + tx] = 0.f; }
    if (tid < 7) wk[tid] = w7[c * 7 + tid];
    else if (tid < 18) wk[tid] = w11[c * 11 + (tid - 7)];
    __syncthreads();
    float bb = b7[c] + b11[c];
    float o[4];
    #pragma unroll
    for (int u = 0; u < 4; ++u) {
        int wpos = tx * 4 + u;
        float acc = bb;
        #pragma unroll
        for (int k = 0; k < 7; ++k)  acc += s[ty][wpos + 5 + k] * wk[k];
        #pragma unroll
        for (int k = 0; k < 11; ++k) acc += s[ty][wpos + 3 + k] * wk[7 + k];
        o[u] = acc;
    }
    *(float4*)&y[rowbase + tx * 4] = make_float4(o[0], o[1], o[2], o[3]);
}

// ----------------- norm scratch mgmt -----------------
__global__ void zero_kernel()
{
    int i = blockIdx.x * 256 + threadIdx.x;
    if (i < 4 * BNCNT * 256) (&g_nsq[0][0])[i] = 0.f;
}

__global__ void scale_kernel()
{
    int i = blockIdx.x * 256 + threadIdx.x;
    if (i < 4 * BNCNT * 256)
        (&g_scale[0][0])[i] = 1.f / fmaxf(sqrtf((&g_nsq[0][0])[i]), 1e-12f);
}

// ================= mma primitives =================
__device__ __forceinline__ void mma_bf16(float* c, const uint32_t* a, uint32_t b0, uint32_t b1)
{
    asm volatile(
        "mma.sync.aligned.m16n8k16.row.col.f32.bf16.bf16.f32 "
        "{%0,%1,%2,%3},{%4,%5,%6,%7},{%8,%9},{%0,%1,%2,%3};"
        : "+f"(c[0]), "+f"(c[1]), "+f"(c[2]), "+f"(c[3])
        : "r"(a[0]), "r"(a[1]), "r"(a[2]), "r"(a[3]), "r"(b0), "r"(b1));
}

__device__ __forceinline__ void cpa16(uint32_t dst, const void* src)
{
    asm volatile("cp.async.cg.shared.global [%0], [%1], 16;" :: "r"(dst), "l"(src));
}
#define CP_COMMIT() asm volatile("cp.async.commit_group;")
#define CP_WAIT(n)  asm volatile("cp.async.wait_group %0;" :: "n"(n))

// ================= 128x128 bf16-split GEMM core =================
#define KP 20
#define SBUF_OFF (4*128*KP)
#define SMEM_BYTES (8*128*KP*4)

__device__ __forceinline__ void load_stage(int buf, const uint4* ah, const uint4* al,
                                           const uint4* bh, const uint4* bl,
                                           uint32_t smbase, int tid)
{
    #pragma unroll
    for (int i = 0; i < 8; ++i) {
        const int hl  = (i >> 1) & 1;
        const int isB = (i >= 4);
        int r = ((i & 1) << 8) + tid;
        int m = r >> 2, q = r & 3;
        const uint4* src = (isB ? (hl ? bl : bh) : (hl ? al : ah)) + m * 32 + q;
        int w = (((buf * 2 + hl) * 128 + m) * KP + q * 4) + (isB ? SBUF_OFF : 0);
        cpa16(smbase + (w << 2), src);
    }
}

__device__ __forceinline__ void gemm_compute(int buf, float (&acc)[4][4][4],
                                             int wM, int wN, int g, int t)
{
    extern __shared__ uint32_t sm[];
    #pragma unroll
    for (int ks = 0; ks < 2; ++ks) {
        int kq = ks * 8 + t;
        uint32_t bh[4][2], bl[4][2];
        #pragma unroll
        for (int nf = 0; nf < 4; ++nf) {
            int n = wN * 32 + nf * 8 + g;
            const uint32_t* pbh = &sm[SBUF_OFF + ((buf * 2 + 0) * 128 + n) * KP];
            const uint32_t* pbl = &sm[SBUF_OFF + ((buf * 2 + 1) * 128 + n) * KP];
            bh[nf][0] = pbh[kq]; bh[nf][1] = pbh[kq + 4];
            bl[nf][0] = pbl[kq]; bl[nf][1] = pbl[kq + 4];
        }
        #pragma unroll
        for (int mf = 0; mf < 4; ++mf) {
            int rrow = wM * 64 + mf * 16 + g;
            const uint32_t* pah = &sm[((buf * 2 + 0) * 128 + rrow) * KP];
            const uint32_t* pal = &sm[((buf * 2 + 1) * 128 + rrow) * KP];
            uint32_t ah4[4] = { pah[kq], pah[8 * KP + kq], pah[kq + 4], pah[8 * KP + kq + 4] };
            uint32_t al4[4] = { pal[kq], pal[8 * KP + kq], pal[kq + 4], pal[8 * KP + kq + 4] };
            #pragma unroll
            for (int nf = 0; nf < 4; ++nf) {
                mma_bf16(acc[mf][nf], ah4, bh[nf][0], bh[nf][1]);
                mma_bf16(acc[mf][nf], al4, bh[nf][0], bh[nf][1]);
                mma_bf16(acc[mf][nf], ah4, bl[nf][0], bl[nf][1]);
            }
        }
    }
}

__device__ __forceinline__ void gemm_run(float (&acc)[4][4][4],
    const uint4* ah, const uint4* al, const uint4* bh, const uint4* bl,
    int nkt, int ps4, uint32_t smbase, int tid, int wM, int wN, int g, int t)
{
    load_stage(0, ah, al, bh, bl, smbase, tid);
    CP_COMMIT();
    for (int kt = 0; kt < nkt; ++kt) {
        int nx = kt + 1;
        if (nx < nkt) {
            int off = (nx >> 3) * ps4 + (nx & 7) * 4;
            load_stage(nx & 1, ah + off, al + off, bh + off, bl + off, smbase, tid);
            CP_COMMIT();
            CP_WAIT(1);
        } else {
            CP_WAIT(0);
        }
        __syncthreads();
        gemm_compute(kt & 1, acc, wM, wN, g, t);
        __syncthreads();
    }
}

// score: C = A @ B' over 12 planes (K = 3072)
__global__ void __launch_bounds__(256) score_mma(
    const __nv_bfloat16* __restrict__ Ah, const __nv_bfloat16* __restrict__ Al,
    const __nv_bfloat16* __restrict__ Bh, const __nv_bfloat16* __restrict__ Bl,
    float* __restrict__ C)
{
    extern __shared__ uint32_t sm[];
    uint32_t smbase = (uint32_t)__cvta_generic_to_shared(sm);
    int tid = threadIdx.x, lane = tid & 31, wid = tid >> 5;
    int wM = wid >> 2, wN = wid & 3, g = lane >> 2, t = lane & 3;
    int bn = blockIdx.y;
    long po = (long)((bn >> 3) * CC + (bn & 7) * CPH) << 16;
    int row0 = (blockIdx.x >> 1) << 7;
    int col0 = (blockIdx.x & 1) << 7;
    const uint4* ah = (const uint4*)(Ah + po) + row0 * 32;
    const uint4* al = (const uint4*)(Al + po) + row0 * 32;
    const uint4* bh = (const uint4*)(Bh + po) + col0 * 32;
    const uint4* bl = (const uint4*)(Bl + po) + col0 * 32;
    float acc[4][4][4];
    #pragma unroll
    for (int a = 0; a < 4; ++a)
        #pragma unroll
        for (int b = 0; b < 4; ++b)
            #pragma unroll
            for (int d = 0; d < 4; ++d) acc[a][b][d] = 0.f;

    gemm_run(acc, ah, al, bh, bl, 96, 8192, smbase, tid, wM, wN, g, t);

    float* Cp = C + ((long)bn << 16);
    int rbase = row0 + wM * 64 + g;
    int cbase = col0 + wN * 32 + 2 * t;
    #pragma unroll
    for (int mf = 0; mf < 4; ++mf) {
        int r = rbase + mf * 16;
        #pragma unroll
        for (int nf = 0; nf < 4; ++nf) {
            int cc = cbase + nf * 8;
            *(float2*)&Cp[(long)r * 256 + cc] = make_float2(acc[mf][nf][0], acc[mf][nf][1]);
            *(float2*)&Cp[(long)(r + 8) * 256 + cc] = make_float2(acc[mf][nf][2], acc[mf][nf][3]);
        }
    }
}

// av (merged): M_c = P1 @ X1T'_c + X2_c @ P2' + residual(O2T*s1 + O1T*s2)
__global__ void __launch_bounds__(256) av_mma(
    const __nv_bfloat16* __restrict__ P1h, const __nv_bfloat16* __restrict__ P1l,
    const __nv_bfloat16* __restrict__ X1Th, const __nv_bfloat16* __restrict__ X1Tl,
    const __nv_bfloat16* __restrict__ X2h, const __nv_bfloat16* __restrict__ X2l,
    const __nv_bfloat16* __restrict__ P2h, const __nv_bfloat16* __restrict__ P2l,
    const __nv_bfloat16* __restrict__ O1Th, const __nv_bfloat16* __restrict__ O1Tl,
    const __nv_bfloat16* __restrict__ O2Th, const __nv_bfloat16* __restrict__ O2Tl,
    const float* __restrict__ s1, const float* __restrict__ s2,
    float* __restrict__ M)
{
    extern __shared__ uint32_t sm[];
    uint32_t smbase = (uint32_t)__cvta_generic_to_shared(sm);
    int tid = threadIdx.x, lane = tid & 31, wid = tid >> 5;
    int wM = wid >> 2, wN = wid & 3, g = lane >> 2, t = lane & 3;
    int bn = blockIdx.z, c = blockIdx.y;
    long po = (long)((bn >> 3) * CC + (bn & 7) * CPH + c) << 16;
    long so = (long)bn << 16;
    int row0 = (blockIdx.x >> 1) << 7;
    int col0 = (blockIdx.x & 1) << 7;
    float acc[4][4][4];
    #pragma unroll
    for (int a = 0; a < 4; ++a)
        #pragma unroll
        for (int b = 0; b < 4; ++b)
            #pragma unroll
            for (int d = 0; d < 4; ++d) acc[a][b][d] = 0.f;

    gemm_run(acc, (const uint4*)(P1h + so) + row0 * 32, (const uint4*)(P1l + so) + row0 * 32,
                  (const uint4*)(X1Th + po) + col0 * 32, (const uint4*)(X1Tl + po) + col0 * 32,
             8, 0, smbase, tid, wM, wN, g, t);
    gemm_run(acc, (const uint4*)(X2h + po) + row0 * 32, (const uint4*)(X2l + po) + row0 * 32,
                  (const uint4*)(P2h + so) + col0 * 32, (const uint4*)(P2l + so) + col0 * 32,
             8, 0, smbase, tid, wM, wN, g, t);

    const uint32_t* pO1h = (const uint32_t*)(O1Th + po);
    const uint32_t* pO1l = (const uint32_t*)(O1Tl + po);
    const uint32_t* pO2h = (const uint32_t*)(O2Th + po);
    const uint32_t* pO2l = (const uint32_t*)(O2Tl + po);
    const float* s1p = s1 + bn * 256;
    const float* s2p = s2 + bn * 256;
    float* Mp = M + po;
    int rbase = row0 + wM * 64 + g;
    int cbase = col0 + wN * 32 + 2 * t;
    #pragma unroll
    for (int mf = 0; mf < 4; ++mf) {
        int r = rbase + mf * 16;
        float s1a = s1p[r], s1b = s1p[r + 8];
        #pragma unroll
        for (int nf = 0; nf < 4; ++nf) {
            int cc = cbase + nf * 8;
            float s2a = s2p[cc], s2b = s2p[cc + 1];
            long q0 = ((long)r * 256 + cc) >> 1;
            long q1 = ((long)(r + 8) * 256 + cc) >> 1;
            float2 o1a = upk2(pO1h[q0], pO1l[q0]);
            float2 o2a = upk2(pO2h[q0], pO2l[q0]);
            float2 o1b = upk2(pO1h[q1], pO1l[q1]);
            float2 o2b = upk2(pO2h[q1], pO2l[q1]);
            float v0 = acc[mf][nf][0] + o2a.x * s1a + o1a.x * s2a;
            float v1 = acc[mf][nf][1] + o2a.y * s1a + o1a.y * s2b;
            float v2 = acc[mf][nf][2] + o2b.x * s1b + o1b.x * s2a;
            float v3 = acc[mf][nf][3] + o2b.y * s1b + o1b.y * s2b;
            *(float2*)&Mp[(long)r * 256 + cc] = make_float2(v0, v1);
            *(float2*)&Mp[(long)(r + 8) * 256 + cc] = make_float2(v2, v3);
        }
    }
}

// ================= tensor-core 1x1 conv (96x96) =================
#define PKP 50
#define PCH 128
#define PCPB 4
#define PSMEM ((2*96*PKP + 2*PCH*PKP)*4)

__global__ void __launch_bounds__(256) pconv_mma(
    const float* __restrict__ X, const float* __restrict__ Wt, const float* __restrict__ bias,
    float* __restrict__ Y, const float* __restrict__ add1, const float* __restrict__ add2,
    float bscale, __nv_bfloat16* __restrict__ hi, __nv_bfloat16* __restrict__ lo)
{
    extern __shared__ uint32_t psm[];
    uint32_t (*sW)[96][PKP] = (uint32_t(*)[96][PKP])psm;
    uint32_t (*sB)[PCH][PKP] = (uint32_t(*)[PCH][PKP])(psm + 2 * 96 * PKP);
    int tid = threadIdx.x, lane = tid & 31, wid = tid >> 5;
    int g = lane >> 2, t = lane & 3;
    int m0 = (wid >> 2) * 48, n0 = (wid & 3) * 32;
    long bbase = ((long)blockIdx.y * CC) << 16;
    int pos0 = blockIdx.x * (PCH * PCPB);

    for (int pidx = tid; pidx < 96 * 48; pidx += 256) {
        int o = pidx / 48, q = pidx - o * 48;
        float2 wv = *(const float2*)&Wt[o * 96 + 2 * q];
        uint32_t h, l; split2(wv.x, wv.y, h, l);
        sW[0][o][q] = h; sW[1][o][q] = l;
    }

    int bnn = tid & 127, kh = (tid >> 7) * 48;
    float v[48];
    const float* Xp = X + bbase + ((long)kh << 16) + pos0 + bnn;
    #pragma unroll
    for (int k = 0; k < 48; ++k) v[k] = Xp[(long)k << 16];

    for (int ch = 0; ch < PCPB; ++ch) {
        __syncthreads();
        #pragma unroll
        for (int q = 0; q < 24; ++q) {
            uint32_t h, l; split2(v[2 * q], v[2 * q + 1], h, l);
            sB[0][bnn][(kh >> 1) + q] = h;
            sB[1][bnn][(kh >> 1) + q] = l;
        }
        __syncthreads();
        if (ch + 1 < PCPB) {
            const float* Xn = Xp + (ch + 1) * PCH;
            #pragma unroll
            for (int k = 0; k < 48; ++k) v[k] = Xn[(long)k << 16];
        }
        float acc[3][4][4];
        #pragma unroll
        for (int a = 0; a < 3; ++a)
            #pragma unroll
            for (int b = 0; b < 4; ++b)
                #pragma unroll
                for (int d = 0; d < 4; ++d) acc[a][b][d] = 0.f;

        #pragma unroll
        for (int s = 0; s < 6; ++s) {
            int kq = s * 8 + t;
            uint32_t bh[4][2], bl[4][2];
            #pragma unroll
            for (int nf = 0; nf < 4; ++nf) {
                int n = n0 + nf * 8 + g;
                bh[nf][0] = sB[0][n][kq]; bh[nf][1] = sB[0][n][kq + 4];
                bl[nf][0] = sB[1][n][kq]; bl[nf][1] = sB[1][n][kq + 4];
            }
            #pragma unroll
            for (int mf = 0; mf < 3; ++mf) {
                int m = m0 + mf * 16 + g;
                uint32_t ah4[4] = { sW[0][m][kq], sW[0][m + 8][kq], sW[0][m][kq + 4], sW[0][m + 8][kq + 4] };
                uint32_t al4[4] = { sW[1][m][kq], sW[1][m + 8][kq], sW[1][m][kq + 4], sW[1][m + 8][kq + 4] };
                #pragma unroll
                for (int nf = 0; nf < 4; ++nf) {
                    mma_bf16(acc[mf][nf], ah4, bh[nf][0], bh[nf][1]);
                    mma_bf16(acc[mf][nf], al4, bh[nf][0], bh[nf][1]);
                    mma_bf16(acc[mf][nf], ah4, bl[nf][0], bl[nf][1]);
                }
            }
        }
        int posc = pos0 + ch * PCH;
        #pragma unroll
        for (int mf = 0; mf < 3; ++mf) {
            int o = m0 + mf * 16 + g;
            float b0v = bias[o] * bscale, b1v = bias[o + 8] * bscale;
            #pragma unroll
            for (int nf = 0; nf < 4; ++nf) {
                int n = posc + n0 + nf * 8 + 2 * t;
                long i0 = bbase + ((long)o << 16) + n;
                long i1 = bbase + ((long)(o + 8) << 16) + n;
                float r0 = acc[mf][nf][0] + b0v, r1 = acc[mf][nf][1] + b0v;
                float r2 = acc[mf][nf][2] + b1v, r3 = acc[mf][nf][3] + b1v;
                if (add1) {
                    float2 a0 = *(const float2*)&add1[i0], b0 = *(const float2*)&add2[i0];
                    float2 a1 = *(const float2*)&add1[i1], b1 = *(const float2*)&add2[i1];
                    r0 += a0.x + b0.x; r1 += a0.y + b0.y;
                    r2 += a1.x + b1.x; r3 += a1.y + b1.y;
                }
                *(float2*)&Y[i0] = make_float2(r0, r1);
                *(float2*)&Y[i1] = make_float2(r2, r3);
                if (hi) {
                    uint32_t hh, ll;
                    split2(r0, r1, hh, ll);
                    ((uint32_t*)hi)[i0 >> 1] = hh; ((uint32_t*)lo)[i0 >> 1] = ll;
                    split2(r2, r3, hh, ll);
                    ((uint32_t*)hi)[i1 >> 1] = hh; ((uint32_t*)lo)[i1 >> 1] = ll;
                }
            }
        }
    }
}

// ----------------- softmax (4 rows/block, natural layout, packed split output) -----------------
__global__ void softmax_kernel(
    const float* __restrict__ S, const float* __restrict__ sq, const float* __restrict__ sk,
    __nv_bfloat16* __restrict__ Ph, __nv_bfloat16* __restrict__ Pl)
{
    int bn = blockIdx.y, j2 = threadIdx.x;   // j2: 0..127
    int i0 = blockIdx.x * 4;
    float2 kk = *(const float2*)&sk[bn * 256 + 2 * j2];
    __shared__ float red[4];
    int lane = j2 & 31, warp = j2 >> 5;
    #pragma unroll
    for (int r = 0; r < 4; ++r) {
        int i = i0 + r;
        long base = ((long)bn << 16) + (long)i * 256;
        float2 vv = *(const float2*)&S[base + 2 * j2];
        float qi = sq[bn * 256 + i];
        float v0 = vv.x * qi * kk.x;
        float v1 = vv.y * qi * kk.y;
        float m = fmaxf(v0, v1);
        #pragma unroll
        for (int o = 16; o; o >>= 1) m = fmaxf(m, __shfl_xor_sync(0xffffffffu, m, o));
        if (lane == 0) red[warp] = m;
        __syncthreads();
        m = fmaxf(fmaxf(red[0], red[1]), fmaxf(red[2], red[3]));
        float e0 = expf(v0 - m), e1 = expf(v1 - m);
        float s = e0 + e1;
        #pragma unroll
        for (int o = 16; o; o >>= 1) s += __shfl_xor_sync(0xffffffffu, s, o);
        __syncthreads();
        if (lane == 0) red[warp] = s;
        __syncthreads();
        s = red[0] + red[1] + red[2] + red[3];
        float inv = 1.f / s;
        uint32_t h, l; split2(e0 * inv, e1 * inv, h, l);
        ((uint32_t*)Ph)[(base >> 1) + j2] = h;
        ((uint32_t*)Pl)[(base >> 1) + j2] = l;
        __syncthreads();
    }
}

// ----------------- host launcher -----------------
extern "C" void kernel_launch(void* const* d_in, const int* in_sizes, int n_in,
                              void* d_out, int out_size)
{
    const float* x1    = (const float*)d_in[0];
    const float* x2    = (const float*)d_in[1];
    const float* ln1w  = (const float*)d_in[2];
    const float* ln1b  = (const float*)d_in[3];
    const float* ln2w  = (const float*)d_in[4];
    const float* ln2b  = (const float*)d_in[5];
    const float* projw = (const float*)d_in[6];
    const float* projb = (const float*)d_in[7];
    const float* c11w  = (const float*)d_in[8];
    const float* c11b  = (const float*)d_in[9];
    const float* c12w  = (const float*)d_in[10];
    const float* c12b  = (const float*)d_in[11];
    const float* c21w  = (const float*)d_in[12];
    const float* c21b  = (const float*)d_in[13];
    const float* c22w  = (const float*)d_in[14];
    const float* c22b  = (const float*)d_in[15];

    void* p;
    cudaGetSymbolAddress(&p, g_x1ln); float* x1ln = (float*)p;
    cudaGetSymbolAddress(&p, g_x2ln); float* x2ln = (float*)p;
    cudaGetSymbolAddress(&p, g_tmp);  float* tmp  = (float*)p;
    cudaGetSymbolAddress(&p, g_tmp2); float* tmp2 = (float*)p;
    cudaGetSymbolAddress(&p, g_out1); float* out1 = (float*)p;
    cudaGetSymbolAddress(&p, g_out2); float* out2 = (float*)p;
    cudaGetSymbolAddress(&p, g_M);    float* Mbuf = (float*)p;
    cudaGetSymbolAddress(&p, g_S1);   float* S1   = (float*)p;
    cudaGetSymbolAddress(&p, g_S2);   float* S2   = (float*)p;
    cudaGetSymbolAddress(&p, g_scale); float* sc  = (float*)p;
    __nv_bfloat16 *X1h,*X1l,*X2h,*X2l,*O1h,*O1l,*X1Th,*X1Tl,*X2Th,*X2Tl,*O1Th,*O1Tl,*O2Th,*O2Tl,*P1h,*P1l,*P2h,*P2l;
    cudaGetSymbolAddress(&p, g_X1h);  X1h  = (__nv_bfloat16*)p;
    cudaGetSymbolAddress(&p, g_X1l);  X1l  = (__nv_bfloat16*)p;
    cudaGetSymbolAddress(&p, g_X2h);  X2h  = (__nv_bfloat16*)p;
    cudaGetSymbolAddress(&p, g_X2l);  X2l  = (__nv_bfloat16*)p;
    cudaGetSymbolAddress(&p, g_O1h);  O1h  = (__nv_bfloat16*)p;
    cudaGetSymbolAddress(&p, g_O1l);  O1l  = (__nv_bfloat16*)p;
    cudaGetSymbolAddress(&p, g_X1Th); X1Th = (__nv_bfloat16*)p;
    cudaGetSymbolAddress(&p, g_X1Tl); X1Tl = (__nv_bfloat16*)p;
    cudaGetSymbolAddress(&p, g_X2Th); X2Th = (__nv_bfloat16*)p;
    cudaGetSymbolAddress(&p, g_X2Tl); X2Tl = (__nv_bfloat16*)p;
    cudaGetSymbolAddress(&p, g_O1Th); O1Th = (__nv_bfloat16*)p;
    cudaGetSymbolAddress(&p, g_O1Tl); O1Tl = (__nv_bfloat16*)p;
    cudaGetSymbolAddress(&p, g_O2Th); O2Th = (__nv_bfloat16*)p;
    cudaGetSymbolAddress(&p, g_O2Tl); O2Tl = (__nv_bfloat16*)p;
    cudaGetSymbolAddress(&p, g_P1h);  P1h  = (__nv_bfloat16*)p;
    cudaGetSymbolAddress(&p, g_P1l);  P1l  = (__nv_bfloat16*)p;
    cudaGetSymbolAddress(&p, g_P2h);  P2h  = (__nv_bfloat16*)p;
    cudaGetSymbolAddress(&p, g_P2l);  P2l  = (__nv_bfloat16*)p;
    const int NS = BNCNT * 256;

    static cudaStream_t sA = nullptr, sB = nullptr, sZ = nullptr;
    static cudaEvent_t eFork, eZ, eL1, eL2, eX2T, eO1T, eO2T, eSc, eP1;
    static int inited = 0;
    if (!inited) {
        cudaStreamCreateWithFlags(&sA, cudaStreamNonBlocking);
        cudaStreamCreateWithFlags(&sB, cudaStreamNonBlocking);
        cudaStreamCreateWithFlags(&sZ, cudaStreamNonBlocking);
        cudaEventCreateWithFlags(&eFork, cudaEventDisableTiming);
        cudaEventCreateWithFlags(&eZ,    cudaEventDisableTiming);
        cudaEventCreateWithFlags(&eL1,   cudaEventDisableTiming);
        cudaEventCreateWithFlags(&eL2,   cudaEventDisableTiming);
        cudaEventCreateWithFlags(&eX2T,  cudaEventDisableTiming);
        cudaEventCreateWithFlags(&eO1T,  cudaEventDisableTiming);
        cudaEventCreateWithFlags(&eO2T,  cudaEventDisableTiming);
        cudaEventCreateWithFlags(&eSc,   cudaEventDisableTiming);
        cudaEventCreateWithFlags(&eP1,   cudaEventDisableTiming);
        cudaFuncSetAttribute(score_mma, cudaFuncAttributeMaxDynamicSharedMemorySize, SMEM_BYTES);
        cudaFuncSetAttribute(av_mma,   cudaFuncAttributeMaxDynamicSharedMemorySize, SMEM_BYTES);
        cudaFuncSetAttribute(pconv_mma, cudaFuncAttributeMaxDynamicSharedMemorySize, PSMEM);
        cudaFuncSetAttribute(ln_kernel, cudaFuncAttributeMaxDynamicSharedMemorySize, 98304);
        inited = 1;
    }

    // fork auxiliary streams off the main (capture) stream
    cudaEventRecord(eFork, 0);
    cudaStreamWaitEvent(sA, eFork, 0);
    cudaStreamWaitEvent(sB, eFork, 0);
    cudaStreamWaitEvent(sZ, eFork, 0);

    // sZ: zero norm accumulators
    zero_kernel<<<128, 256, 0, sZ>>>();
    cudaEventRecord(eZ, sZ);

    // main (x1 branch): ln1
    ln_kernel<<<dim3(256, 4), 256, 98304, 0>>>(x1, ln1w, ln1b, x1ln, X1h, X1l);
    cudaEventRecord(eL1, 0);

    // sB (x2 branch): ln2
    ln_kernel<<<dim3(256, 4), 256, 98304, sB>>>(x2, ln2w, ln2b, x2ln, X2h, X2l);
    cudaEventRecord(eL2, sB);

    // sA: the two X transposes (+ norms 0 and 3)
    cudaStreamWaitEvent(sA, eZ, 0);
    cudaStreamWaitEvent(sA, eL1, 0);
    splitT_kernel<<<dim3(32, 384), dim3(32, 8), 0, sA>>>(x1ln, X1Th, X1Tl, 0, -1);
    cudaStreamWaitEvent(sA, eL2, 0);
    splitT_kernel<<<dim3(32, 384), dim3(32, 8), 0, sA>>>(x2ln, X2Th, X2Tl, -1, 3);
    cudaEventRecord(eX2T, sA);

    // main: x1 branch continues
    dw_kernel<<<dim3(64, 96, 4), 256, 0, 0>>>(x1ln, c11w, c11b, c12w, c12b, tmp);
    pconv_mma<<<dim3(128, 4), 256, PSMEM, 0>>>(tmp, projw, projb, out1, nullptr, nullptr, 1.f, O1h, O1l);
    cudaStreamWaitEvent(0, eZ, 0);
    splitT_kernel<<<dim3(32, 384), dim3(32, 8), 0, 0>>>(out1, O1Th, O1Tl, 2, -1);   // 2=sq2 row out1
    cudaEventRecord(eO1T, 0);

    // sB: x2 branch continues
    dw_kernel<<<dim3(64, 96, 4), 256, 0, sB>>>(x2ln, c21w, c21b, c22w, c22b, tmp2);
    pconv_mma<<<dim3(128, 4), 256, PSMEM, sB>>>(tmp2, projw, projb, out2, nullptr, nullptr, 1.f, nullptr, nullptr);
    cudaStreamWaitEvent(sB, eZ, 0);
    splitT_kernel<<<dim3(32, 384), dim3(32, 8), 0, sB>>>(out2, O2Th, O2Tl, -1, 1);  // 1=sq1 col out2
    cudaEventRecord(eO2T, sB);

    // sA: scale after all 4 norm contributors
    cudaStreamWaitEvent(sA, eO1T, 0);
    cudaStreamWaitEvent(sA, eO2T, 0);
    scale_kernel<<<128, 256, 0, sA>>>();
    cudaEventRecord(eSc, sA);

    // main: S2 = O1 @ X2T' — compute under sB's remaining memory work
    cudaStreamWaitEvent(0, eX2T, 0);
    score_mma<<<dim3(4, 32), 256, SMEM_BYTES, 0>>>(O1h, O1l, X2Th, X2Tl, S2);

    // sB: S1 = O2T @ X1' then softmax1 -> P1
    cudaStreamWaitEvent(sB, eL1, 0);
    score_mma<<<dim3(4, 32), 256, SMEM_BYTES, sB>>>(O2Th, O2Tl, X1h, X1l, S1);
    cudaStreamWaitEvent(sB, eSc, 0);
    softmax_kernel<<<dim3(64, 32), 128, 0, sB>>>(S1, sc + 1 * NS, sc + 0 * NS, P1h, P1l);
    cudaEventRecord(eP1, sB);

    // main: softmax2 -> P2, then merged AV (waits P1; single M write, no RMW)
    cudaStreamWaitEvent(0, eSc, 0);
    softmax_kernel<<<dim3(64, 32), 128, 0, 0>>>(S2, sc + 2 * NS, sc + 3 * NS, P2h, P2l);
    cudaStreamWaitEvent(0, eP1, 0);
    av_mma<<<dim3(4, 12, 32), 256, SMEM_BYTES, 0>>>(P1h, P1l, X1Th, X1Tl, X2h, X2l, P2h, P2l,
                                                    O1Th, O1Tl, O2Th, O2Tl,
                                                    sc + 1 * NS, sc + 2 * NS, Mbuf);

    // main: final pconv (x2ln ready transitively via eX2T -> eL2)
    pconv_mma<<<dim3(128, 4), 256, PSMEM, 0>>>(Mbuf, projw, projb, (float*)d_out,
                                               x1ln, x2ln, 2.f, nullptr, nullptr);
}

// round 15
// speedup vs baseline: 1.0760x; 1.0258x over previous
#include <cuda_runtime.h>
#include <cuda_bf16.h>
#include <math.h>
#include <stdint.h>

// Problem constants
#define BB 4
#define CC 96
#define HWSZ 65536
#define NHEAD 8
#define CPH 12
#define NTOT (BB*CC*HWSZ)
#define BNCNT (BB*NHEAD)
#define SSZ (BNCNT*HWSZ)

// ----------------- scratch -----------------
__device__ float g_x1ln[NTOT];
__device__ float g_x2ln[NTOT];
__device__ float g_tmp [NTOT];
__device__ float g_tmp2[NTOT];
__device__ float g_out1[NTOT];
__device__ float g_out2[NTOT];
__device__ float g_M   [NTOT];
__device__ float g_S1  [SSZ];
__device__ float g_S2  [SSZ];
__device__ float g_nsq  [4][BNCNT*256];
__device__ float g_scale[4][BNCNT*256];

// bf16 split buffers (hi/lo)
__device__ __nv_bfloat16 g_X1h[NTOT], g_X1l[NTOT];
__device__ __nv_bfloat16 g_X2h[NTOT], g_X2l[NTOT];
__device__ __nv_bfloat16 g_O1h[NTOT], g_O1l[NTOT];
__device__ __nv_bfloat16 g_X1Th[NTOT], g_X1Tl[NTOT];
__device__ __nv_bfloat16 g_X2Th[NTOT], g_X2Tl[NTOT];
__device__ __nv_bfloat16 g_O1Th[NTOT], g_O1Tl[NTOT];
__device__ __nv_bfloat16 g_O2Th[NTOT], g_O2Tl[NTOT];
__device__ __nv_bfloat16 g_P1h[SSZ], g_P1l[SSZ];
__device__ __nv_bfloat16 g_P2h[SSZ], g_P2l[SSZ];

// ----------------- small helpers -----------------
__device__ __forceinline__ void split_store(float v, __nv_bfloat16* hi, __nv_bfloat16* lo, long idx)
{
    __nv_bfloat16 h = __float2bfloat16(v);
    hi[idx] = h;
    lo[idx] = __float2bfloat16(v - __bfloat162float(h));
}

__device__ __forceinline__ void split2(float a, float b, uint32_t& h, uint32_t& l)
{
    __nv_bfloat162 hv = __floats2bfloat162_rn(a, b);
    h = *(uint32_t*)&hv;
    __nv_bfloat162 lv = __floats2bfloat162_rn(a - __bfloat162float(hv.x),
                                              b - __bfloat162float(hv.y));
    l = *(uint32_t*)&lv;
}

__device__ __forceinline__ float2 upk2(uint32_t h, uint32_t l)
{
    __nv_bfloat162 hh = *(__nv_bfloat162*)&h;
    __nv_bfloat162 ll = *(__nv_bfloat162*)&l;
    return make_float2(__bfloat162float(hh.x) + __bfloat162float(ll.x),
                       __bfloat162float(hh.y) + __bfloat162float(ll.y));
}

// ----------------- LayerNorm (channel dim), smem-cached, fused bf16 split -----------------
__global__ void ln_kernel(const float* __restrict__ x, const float* __restrict__ w,
                          const float* __restrict__ bsh, float* __restrict__ y,
                          __nv_bfloat16* __restrict__ hi, __nv_bfloat16* __restrict__ lo)
{
    extern __shared__ float lnsm[];   // 96*256 floats
    int tid = threadIdx.x;
    int pos = blockIdx.x * 256 + tid;
    long base = ((long)blockIdx.y * CC) << 16;
    float s = 0.f, ss = 0.f;
    #pragma unroll 8
    for (int c = 0; c < CC; ++c) {
        float v = x[base + ((long)c << 16) + pos];
        lnsm[c * 256 + tid] = v;
        s += v; ss += v * v;
    }
    float mu = s * (1.f / 96.f);
    float var = ss * (1.f / 96.f) - mu * mu;
    float inv = rsqrtf(var + 1e-5f);
    #pragma unroll 8
    for (int c = 0; c < CC; ++c) {
        long id = base + ((long)c << 16) + pos;
        float v = (lnsm[c * 256 + tid] - mu) * inv * w[c] + bsh[c];
        y[id] = v;
        split_store(v, hi, lo, id);
    }
}

// ----------------- transpose+split with cheap fused row/col norms -----------------
__global__ void splitT_kernel(const float* __restrict__ X,
                              __nv_bfloat16* __restrict__ hiT, __nv_bfloat16* __restrict__ loT,
                              int rw, int cw)
{
    __shared__ float ts[64][33];
    __shared__ float colacc[32];
    int p = blockIdx.y;                 // plane 0..383
    int b = p / 96, c = p - b * 96, head = c / 12;
    int nbase = (b * 8 + head) * 256;
    long po = (long)p << 16;
    int h0 = (blockIdx.x >> 3) << 6;
    int w0 = (blockIdx.x & 7) << 5;
    int tx = threadIdx.x, ty = threadIdx.y;
    int tid = ty * 32 + tx;
    if (ty == 0) colacc[tx] = 0.f;
    float cs = 0.f;
    #pragma unroll
    for (int i = 0; i < 8; ++i) {
        int r = ty * 8 + i;
        float v = X[po + (long)(h0 + r) * 256 + w0 + tx];
        ts[r][tx] = v;
        cs += v * v;
    }
    __syncthreads();
    if (cw >= 0) atomicAdd(&colacc[tx], cs);
    if (rw >= 0 && tid < 64) {
        float rs = 0.f;
        #pragma unroll
        for (int q = 0; q < 32; ++q) { float v = ts[tid][q]; rs += v * v; }
        atomicAdd(&g_nsq[rw][nbase + h0 + tid], rs);
    }
    uint32_t* hp = (uint32_t*)hiT;
    uint32_t* lp = (uint32_t*)loT;
    #pragma unroll
    for (int j = 0; j < 4; ++j) {
        int wr = ty * 4 + j;
        float v0 = ts[2 * tx][wr], v1 = ts[2 * tx + 1][wr];
        uint32_t h, l; split2(v0, v1, h, l);
        long oidx = (po + (long)(w0 + wr) * 256 + h0) >> 1;
        hp[oidx + tx] = h;
        lp[oidx + tx] = l;
    }
    if (cw >= 0) {
        __syncthreads();
        if (ty == 0) atomicAdd(&g_nsq[cw][nbase + w0 + tx], colacc[tx]);
    }
}

// ----------------- depthwise (1,7)+(1,11) conv along W, 4 rows/block -----------------
__global__ void dw_kernel(const float* __restrict__ x,
                          const float* __restrict__ w7, const float* __restrict__ b7,
                          const float* __restrict__ w11, const float* __restrict__ b11,
                          float* __restrict__ y)
{
    int hq = blockIdx.x, c = blockIdx.y, b = blockIdx.z;
    long pb = (((long)(b * CC + c)) << 16);
    __shared__ float s[4][272];
    __shared__ float wk[18];
    int tid = threadIdx.x;
    int ty = tid >> 6, tx = tid & 63;
    long rowbase = pb + ((long)(4 * hq + ty) << 8);
    *(float4*)&s[ty][8 + tx * 4] = *(const float4*)&x[rowbase + tx * 4];
    if (tx < 8) { s[ty][tx] = 0.f; s[ty][264 + tx] = 0.f; }
    if (tid < 7) wk[tid] = w7[c * 7 + tid];
    else if (tid < 18) wk[tid] = w11[c * 11 + (tid - 7)];
    __syncthreads();
    float bb = b7[c] + b11[c];
    float o[4];
    #pragma unroll
    for (int u = 0; u < 4; ++u) {
        int wpos = tx * 4 + u;
        float acc = bb;
        #pragma unroll
        for (int k = 0; k < 7; ++k)  acc += s[ty][wpos + 5 + k] * wk[k];
        #pragma unroll
        for (int k = 0; k < 11; ++k) acc += s[ty][wpos + 3 + k] * wk[7 + k];
        o[u] = acc;
    }
    *(float4*)&y[rowbase + tx * 4] = make_float4(o[0], o[1], o[2], o[3]);
}

// ----------------- norm scratch mgmt -----------------
__global__ void zero_kernel()
{
    int i = blockIdx.x * 256 + threadIdx.x;
    if (i < 4 * BNCNT * 256) (&g_nsq[0][0])[i] = 0.f;
}

__global__ void scale_kernel()
{
    int i = blockIdx.x * 256 + threadIdx.x;
    if (i < 4 * BNCNT * 256)
        (&g_scale[0][0])[i] = 1.f / fmaxf(sqrtf((&g_nsq[0][0])[i]), 1e-12f);
}

// ================= mma primitives =================
__device__ __forceinline__ void mma_bf16(float* c, const uint32_t* a, uint32_t b0, uint32_t b1)
{
    asm volatile(
        "mma.sync.aligned.m16n8k16.row.col.f32.bf16.bf16.f32 "
        "{%0,%1,%2,%3},{%4,%5,%6,%7},{%8,%9},{%0,%1,%2,%3};"
        : "+f"(c[0]), "+f"(c[1]), "+f"(c[2]), "+f"(c[3])
        : "r"(a[0]), "r"(a[1]), "r"(a[2]), "r"(a[3]), "r"(b0), "r"(b1));
}

__device__ __forceinline__ void cpa16(uint32_t dst, const void* src)
{
    asm volatile("cp.async.cg.shared.global [%0], [%1], 16;" :: "r"(dst), "l"(src));
}
#define CP_COMMIT() asm volatile("cp.async.commit_group;")
#define CP_WAIT(n)  asm volatile("cp.async.wait_group %0;" :: "n"(n))

// ================= 128x128 bf16-split GEMM core =================
#define KP 20
#define SBUF_OFF (4*128*KP)
#define SMEM_BYTES (8*128*KP*4)

__device__ __forceinline__ void load_stage(int buf, const uint4* ah, const uint4* al,
                                           const uint4* bh, const uint4* bl,
                                           uint32_t smbase, int tid)
{
    #pragma unroll
    for (int i = 0; i < 8; ++i) {
        const int hl  = (i >> 1) & 1;
        const int isB = (i >= 4);
        int r = ((i & 1) << 8) + tid;
        int m = r >> 2, q = r & 3;
        const uint4* src = (isB ? (hl ? bl : bh) : (hl ? al : ah)) + m * 32 + q;
        int w = (((buf * 2 + hl) * 128 + m) * KP + q * 4) + (isB ? SBUF_OFF : 0);
        cpa16(smbase + (w << 2), src);
    }
}

__device__ __forceinline__ void gemm_compute(int buf, float (&acc)[4][4][4],
                                             int wM, int wN, int g, int t)
{
    extern __shared__ uint32_t sm[];
    #pragma unroll
    for (int ks = 0; ks < 2; ++ks) {
        int kq = ks * 8 + t;
        uint32_t bh[4][2], bl[4][2];
        #pragma unroll
        for (int nf = 0; nf < 4; ++nf) {
            int n = wN * 32 + nf * 8 + g;
            const uint32_t* pbh = &sm[SBUF_OFF + ((buf * 2 + 0) * 128 + n) * KP];
            const uint32_t* pbl = &sm[SBUF_OFF + ((buf * 2 + 1) * 128 + n) * KP];
            bh[nf][0] = pbh[kq]; bh[nf][1] = pbh[kq + 4];
            bl[nf][0] = pbl[kq]; bl[nf][1] = pbl[kq + 4];
        }
        #pragma unroll
        for (int mf = 0; mf < 4; ++mf) {
            int rrow = wM * 64 + mf * 16 + g;
            const uint32_t* pah = &sm[((buf * 2 + 0) * 128 + rrow) * KP];
            const uint32_t* pal = &sm[((buf * 2 + 1) * 128 + rrow) * KP];
            uint32_t ah4[4] = { pah[kq], pah[8 * KP + kq], pah[kq + 4], pah[8 * KP + kq + 4] };
            uint32_t al4[4] = { pal[kq], pal[8 * KP + kq], pal[kq + 4], pal[8 * KP + kq + 4] };
            #pragma unroll
            for (int nf = 0; nf < 4; ++nf) {
                mma_bf16(acc[mf][nf], ah4, bh[nf][0], bh[nf][1]);
                mma_bf16(acc[mf][nf], al4, bh[nf][0], bh[nf][1]);
                mma_bf16(acc[mf][nf], ah4, bl[nf][0], bl[nf][1]);
            }
        }
    }
}

__device__ __forceinline__ void gemm_run(float (&acc)[4][4][4],
    const uint4* ah, const uint4* al, const uint4* bh, const uint4* bl,
    int nkt, int ps4, uint32_t smbase, int tid, int wM, int wN, int g, int t)
{
    load_stage(0, ah, al, bh, bl, smbase, tid);
    CP_COMMIT();
    for (int kt = 0; kt < nkt; ++kt) {
        int nx = kt + 1;
        if (nx < nkt) {
            int off = (nx >> 3) * ps4 + (nx & 7) * 4;
            load_stage(nx & 1, ah + off, al + off, bh + off, bl + off, smbase, tid);
            CP_COMMIT();
            CP_WAIT(1);
        } else {
            CP_WAIT(0);
        }
        __syncthreads();
        gemm_compute(kt & 1, acc, wM, wN, g, t);
        __syncthreads();
    }
}

// score: C = A @ B' over 12 planes (K = 3072)
__global__ void __launch_bounds__(256) score_mma(
    const __nv_bfloat16* __restrict__ Ah, const __nv_bfloat16* __restrict__ Al,
    const __nv_bfloat16* __restrict__ Bh, const __nv_bfloat16* __restrict__ Bl,
    float* __restrict__ C)
{
    extern __shared__ uint32_t sm[];
    uint32_t smbase = (uint32_t)__cvta_generic_to_shared(sm);
    int tid = threadIdx.x, lane = tid & 31, wid = tid >> 5;
    int wM = wid >> 2, wN = wid & 3, g = lane >> 2, t = lane & 3;
    int bn = blockIdx.y;
    long po = (long)((bn >> 3) * CC + (bn & 7) * CPH) << 16;
    int row0 = (blockIdx.x >> 1) << 7;
    int col0 = (blockIdx.x & 1) << 7;
    const uint4* ah = (const uint4*)(Ah + po) + row0 * 32;
    const uint4* al = (const uint4*)(Al + po) + row0 * 32;
    const uint4* bh = (const uint4*)(Bh + po) + col0 * 32;
    const uint4* bl = (const uint4*)(Bl + po) + col0 * 32;
    float acc[4][4][4];
    #pragma unroll
    for (int a = 0; a < 4; ++a)
        #pragma unroll
        for (int b = 0; b < 4; ++b)
            #pragma unroll
            for (int d = 0; d < 4; ++d) acc[a][b][d] = 0.f;

    gemm_run(acc, ah, al, bh, bl, 96, 8192, smbase, tid, wM, wN, g, t);

    float* Cp = C + ((long)bn << 16);
    int rbase = row0 + wM * 64 + g;
    int cbase = col0 + wN * 32 + 2 * t;
    #pragma unroll
    for (int mf = 0; mf < 4; ++mf) {
        int r = rbase + mf * 16;
        #pragma unroll
        for (int nf = 0; nf < 4; ++nf) {
            int cc = cbase + nf * 8;
            *(float2*)&Cp[(long)r * 256 + cc] = make_float2(acc[mf][nf][0], acc[mf][nf][1]);
            *(float2*)&Cp[(long)(r + 8) * 256 + cc] = make_float2(acc[mf][nf][2], acc[mf][nf][3]);
        }
    }
}

// av (merged, batch-chunked): M_c = P1 @ X1T'_c + X2_c @ P2' + residual
__global__ void __launch_bounds__(256) av_mma(
    const __nv_bfloat16* __restrict__ P1h, const __nv_bfloat16* __restrict__ P1l,
    const __nv_bfloat16* __restrict__ X1Th, const __nv_bfloat16* __restrict__ X1Tl,
    const __nv_bfloat16* __restrict__ X2h, const __nv_bfloat16* __restrict__ X2l,
    const __nv_bfloat16* __restrict__ P2h, const __nv_bfloat16* __restrict__ P2l,
    const __nv_bfloat16* __restrict__ O1Th, const __nv_bfloat16* __restrict__ O1Tl,
    const __nv_bfloat16* __restrict__ O2Th, const __nv_bfloat16* __restrict__ O2Tl,
    const float* __restrict__ s1, const float* __restrict__ s2,
    float* __restrict__ M, int bn0)
{
    extern __shared__ uint32_t sm[];
    uint32_t smbase = (uint32_t)__cvta_generic_to_shared(sm);
    int tid = threadIdx.x, lane = tid & 31, wid = tid >> 5;
    int wM = wid >> 2, wN = wid & 3, g = lane >> 2, t = lane & 3;
    int bn = bn0 + blockIdx.z, c = blockIdx.y;
    long po = (long)((bn >> 3) * CC + (bn & 7) * CPH + c) << 16;
    long so = (long)bn << 16;
    int row0 = (blockIdx.x >> 1) << 7;
    int col0 = (blockIdx.x & 1) << 7;
    float acc[4][4][4];
    #pragma unroll
    for (int a = 0; a < 4; ++a)
        #pragma unroll
        for (int b = 0; b < 4; ++b)
            #pragma unroll
            for (int d = 0; d < 4; ++d) acc[a][b][d] = 0.f;

    gemm_run(acc, (const uint4*)(P1h + so) + row0 * 32, (const uint4*)(P1l + so) + row0 * 32,
                  (const uint4*)(X1Th + po) + col0 * 32, (const uint4*)(X1Tl + po) + col0 * 32,
             8, 0, smbase, tid, wM, wN, g, t);
    gemm_run(acc, (const uint4*)(X2h + po) + row0 * 32, (const uint4*)(X2l + po) + row0 * 32,
                  (const uint4*)(P2h + so) + col0 * 32, (const uint4*)(P2l + so) + col0 * 32,
             8, 0, smbase, tid, wM, wN, g, t);

    const uint32_t* pO1h = (const uint32_t*)(O1Th + po);
    const uint32_t* pO1l = (const uint32_t*)(O1Tl + po);
    const uint32_t* pO2h = (const uint32_t*)(O2Th + po);
    const uint32_t* pO2l = (const uint32_t*)(O2Tl + po);
    const float* s1p = s1 + bn * 256;
    const float* s2p = s2 + bn * 256;
    float* Mp = M + po;
    int rbase = row0 + wM * 64 + g;
    int cbase = col0 + wN * 32 + 2 * t;
    #pragma unroll
    for (int mf = 0; mf < 4; ++mf) {
        int r = rbase + mf * 16;
        float s1a = s1p[r], s1b = s1p[r + 8];
        #pragma unroll
        for (int nf = 0; nf < 4; ++nf) {
            int cc = cbase + nf * 8;
            float s2a = s2p[cc], s2b = s2p[cc + 1];
            long q0 = ((long)r * 256 + cc) >> 1;
            long q1 = ((long)(r + 8) * 256 + cc) >> 1;
            float2 o1a = upk2(pO1h[q0], pO1l[q0]);
            float2 o2a = upk2(pO2h[q0], pO2l[q0]);
            float2 o1b = upk2(pO1h[q1], pO1l[q1]);
            float2 o2b = upk2(pO2h[q1], pO2l[q1]);
            float v0 = acc[mf][nf][0] + o2a.x * s1a + o1a.x * s2a;
            float v1 = acc[mf][nf][1] + o2a.y * s1a + o1a.y * s2b;
            float v2 = acc[mf][nf][2] + o2b.x * s1b + o1b.x * s2a;
            float v3 = acc[mf][nf][3] + o2b.y * s1b + o1b.y * s2b;
            *(float2*)&Mp[(long)r * 256 + cc] = make_float2(v0, v1);
            *(float2*)&Mp[(long)(r + 8) * 256 + cc] = make_float2(v2, v3);
        }
    }
}

// ================= tensor-core 1x1 conv (96x96), batch-offset param =================
#define PKP 50
#define PCH 128
#define PCPB 4
#define PSMEM ((2*96*PKP + 2*PCH*PKP)*4)

__global__ void __launch_bounds__(256) pconv_mma(
    const float* __restrict__ X, const float* __restrict__ Wt, const float* __restrict__ bias,
    float* __restrict__ Y, const float* __restrict__ add1, const float* __restrict__ add2,
    float bscale, __nv_bfloat16* __restrict__ hi, __nv_bfloat16* __restrict__ lo, int by0)
{
    extern __shared__ uint32_t psm[];
    uint32_t (*sW)[96][PKP] = (uint32_t(*)[96][PKP])psm;
    uint32_t (*sB)[PCH][PKP] = (uint32_t(*)[PCH][PKP])(psm + 2 * 96 * PKP);
    int tid = threadIdx.x, lane = tid & 31, wid = tid >> 5;
    int g = lane >> 2, t = lane & 3;
    int m0 = (wid >> 2) * 48, n0 = (wid & 3) * 32;
    long bbase = ((long)((by0 + blockIdx.y) * CC)) << 16;
    int pos0 = blockIdx.x * (PCH * PCPB);

    for (int pidx = tid; pidx < 96 * 48; pidx += 256) {
        int o = pidx / 48, q = pidx - o * 48;
        float2 wv = *(const float2*)&Wt[o * 96 + 2 * q];
        uint32_t h, l; split2(wv.x, wv.y, h, l);
        sW[0][o][q] = h; sW[1][o][q] = l;
    }

    int bnn = tid & 127, kh = (tid >> 7) * 48;
    float v[48];
    const float* Xp = X + bbase + ((long)kh << 16) + pos0 + bnn;
    #pragma unroll
    for (int k = 0; k < 48; ++k) v[k] = Xp[(long)k << 16];

    for (int ch = 0; ch < PCPB; ++ch) {
        __syncthreads();
        #pragma unroll
        for (int q = 0; q < 24; ++q) {
            uint32_t h, l; split2(v[2 * q], v[2 * q + 1], h, l);
            sB[0][bnn][(kh >> 1) + q] = h;
            sB[1][bnn][(kh >> 1) + q] = l;
        }
        __syncthreads();
        if (ch + 1 < PCPB) {
            const float* Xn = Xp + (ch + 1) * PCH;
            #pragma unroll
            for (int k = 0; k < 48; ++k) v[k] = Xn[(long)k << 16];
        }
        float acc[3][4][4];
        #pragma unroll
        for (int a = 0; a < 3; ++a)
            #pragma unroll
            for (int b = 0; b < 4; ++b)
                #pragma unroll
                for (int d = 0; d < 4; ++d) acc[a][b][d] = 0.f;

        #pragma unroll
        for (int s = 0; s < 6; ++s) {
            int kq = s * 8 + t;
            uint32_t bh[4][2], bl[4][2];
            #pragma unroll
            for (int nf = 0; nf < 4; ++nf) {
                int n = n0 + nf * 8 + g;
                bh[nf][0] = sB[0][n][kq]; bh[nf][1] = sB[0][n][kq + 4];
                bl[nf][0] = sB[1][n][kq]; bl[nf][1] = sB[1][n][kq + 4];
            }
            #pragma unroll
            for (int mf = 0; mf < 3; ++mf) {
                int m = m0 + mf * 16 + g;
                uint32_t ah4[4] = { sW[0][m][kq], sW[0][m + 8][kq], sW[0][m][kq + 4], sW[0][m + 8][kq + 4] };
                uint32_t al4[4] = { sW[1][m][kq], sW[1][m + 8][kq], sW[1][m][kq + 4], sW[1][m + 8][kq + 4] };
                #pragma unroll
                for (int nf = 0; nf < 4; ++nf) {
                    mma_bf16(acc[mf][nf], ah4, bh[nf][0], bh[nf][1]);
                    mma_bf16(acc[mf][nf], al4, bh[nf][0], bh[nf][1]);
                    mma_bf16(acc[mf][nf], ah4, bl[nf][0], bl[nf][1]);
                }
            }
        }
        int posc = pos0 + ch * PCH;
        #pragma unroll
        for (int mf = 0; mf < 3; ++mf) {
            int o = m0 + mf * 16 + g;
            float b0v = bias[o] * bscale, b1v = bias[o + 8] * bscale;
            #pragma unroll
            for (int nf = 0; nf < 4; ++nf) {
                int n = posc + n0 + nf * 8 + 2 * t;
                long i0 = bbase + ((long)o << 16) + n;
                long i1 = bbase + ((long)(o + 8) << 16) + n;
                float r0 = acc[mf][nf][0] + b0v, r1 = acc[mf][nf][1] + b0v;
                float r2 = acc[mf][nf][2] + b1v, r3 = acc[mf][nf][3] + b1v;
                if (add1) {
                    float2 a0 = *(const float2*)&add1[i0], b0 = *(const float2*)&add2[i0];
                    float2 a1 = *(const float2*)&add1[i1], b1 = *(const float2*)&add2[i1];
                    r0 += a0.x + b0.x; r1 += a0.y + b0.y;
                    r2 += a1.x + b1.x; r3 += a1.y + b1.y;
                }
                *(float2*)&Y[i0] = make_float2(r0, r1);
                *(float2*)&Y[i1] = make_float2(r2, r3);
                if (hi) {
                    uint32_t hh, ll;
                    split2(r0, r1, hh, ll);
                    ((uint32_t*)hi)[i0 >> 1] = hh; ((uint32_t*)lo)[i0 >> 1] = ll;
                    split2(r2, r3, hh, ll);
                    ((uint32_t*)hi)[i1 >> 1] = hh; ((uint32_t*)lo)[i1 >> 1] = ll;
                }
            }
        }
    }
}

// ----------------- softmax (4 rows/block, natural layout, packed split output) -----------------
__global__ void softmax_kernel(
    const float* __restrict__ S, const float* __restrict__ sq, const float* __restrict__ sk,
    __nv_bfloat16* __restrict__ Ph, __nv_bfloat16* __restrict__ Pl)
{
    int bn = blockIdx.y, j2 = threadIdx.x;   // j2: 0..127
    int i0 = blockIdx.x * 4;
    float2 kk = *(const float2*)&sk[bn * 256 + 2 * j2];
    __shared__ float red[4];
    int lane = j2 & 31, warp = j2 >> 5;
    #pragma unroll
    for (int r = 0; r < 4; ++r) {
        int i = i0 + r;
        long base = ((long)bn << 16) + (long)i * 256;
        float2 vv = *(const float2*)&S[base + 2 * j2];
        float qi = sq[bn * 256 + i];
        float v0 = vv.x * qi * kk.x;
        float v1 = vv.y * qi * kk.y;
        float m = fmaxf(v0, v1);
        #pragma unroll
        for (int o = 16; o; o >>= 1) m = fmaxf(m, __shfl_xor_sync(0xffffffffu, m, o));
        if (lane == 0) red[warp] = m;
        __syncthreads();
        m = fmaxf(fmaxf(red[0], red[1]), fmaxf(red[2], red[3]));
        float e0 = expf(v0 - m), e1 = expf(v1 - m);
        float s = e0 + e1;
        #pragma unroll
        for (int o = 16; o; o >>= 1) s += __shfl_xor_sync(0xffffffffu, s, o);
        __syncthreads();
        if (lane == 0) red[warp] = s;
        __syncthreads();
        s = red[0] + red[1] + red[2] + red[3];
        float inv = 1.f / s;
        uint32_t h, l; split2(e0 * inv, e1 * inv, h, l);
        ((uint32_t*)Ph)[(base >> 1) + j2] = h;
        ((uint32_t*)Pl)[(base >> 1) + j2] = l;
        __syncthreads();
    }
}

// ----------------- host launcher -----------------
extern "C" void kernel_launch(void* const* d_in, const int* in_sizes, int n_in,
                              void* d_out, int out_size)
{
    const float* x1    = (const float*)d_in[0];
    const float* x2    = (const float*)d_in[1];
    const float* ln1w  = (const float*)d_in[2];
    const float* ln1b  = (const float*)d_in[3];
    const float* ln2w  = (const float*)d_in[4];
    const float* ln2b  = (const float*)d_in[5];
    const float* projw = (const float*)d_in[6];
    const float* projb = (const float*)d_in[7];
    const float* c11w  = (const float*)d_in[8];
    const float* c11b  = (const float*)d_in[9];
    const float* c12w  = (const float*)d_in[10];
    const float* c12b  = (const float*)d_in[11];
    const float* c21w  = (const float*)d_in[12];
    const float* c21b  = (const float*)d_in[13];
    const float* c22w  = (const float*)d_in[14];
    const float* c22b  = (const float*)d_in[15];

    void* p;
    cudaGetSymbolAddress(&p, g_x1ln); float* x1ln = (float*)p;
    cudaGetSymbolAddress(&p, g_x2ln); float* x2ln = (float*)p;
    cudaGetSymbolAddress(&p, g_tmp);  float* tmp  = (float*)p;
    cudaGetSymbolAddress(&p, g_tmp2); float* tmp2 = (float*)p;
    cudaGetSymbolAddress(&p, g_out1); float* out1 = (float*)p;
    cudaGetSymbolAddress(&p, g_out2); float* out2 = (float*)p;
    cudaGetSymbolAddress(&p, g_M);    float* Mbuf = (float*)p;
    cudaGetSymbolAddress(&p, g_S1);   float* S1   = (float*)p;
    cudaGetSymbolAddress(&p, g_S2);   float* S2   = (float*)p;
    cudaGetSymbolAddress(&p, g_scale); float* sc  = (float*)p;
    __nv_bfloat16 *X1h,*X1l,*X2h,*X2l,*O1h,*O1l,*X1Th,*X1Tl,*X2Th,*X2Tl,*O1Th,*O1Tl,*O2Th,*O2Tl,*P1h,*P1l,*P2h,*P2l;
    cudaGetSymbolAddress(&p, g_X1h);  X1h  = (__nv_bfloat16*)p;
    cudaGetSymbolAddress(&p, g_X1l);  X1l  = (__nv_bfloat16*)p;
    cudaGetSymbolAddress(&p, g_X2h);  X2h  = (__nv_bfloat16*)p;
    cudaGetSymbolAddress(&p, g_X2l);  X2l  = (__nv_bfloat16*)p;
    cudaGetSymbolAddress(&p, g_O1h);  O1h  = (__nv_bfloat16*)p;
    cudaGetSymbolAddress(&p, g_O1l);  O1l  = (__nv_bfloat16*)p;
    cudaGetSymbolAddress(&p, g_X1Th); X1Th = (__nv_bfloat16*)p;
    cudaGetSymbolAddress(&p, g_X1Tl); X1Tl = (__nv_bfloat16*)p;
    cudaGetSymbolAddress(&p, g_X2Th); X2Th = (__nv_bfloat16*)p;
    cudaGetSymbolAddress(&p, g_X2Tl); X2Tl = (__nv_bfloat16*)p;
    cudaGetSymbolAddress(&p, g_O1Th); O1Th = (__nv_bfloat16*)p;
    cudaGetSymbolAddress(&p, g_O1Tl); O1Tl = (__nv_bfloat16*)p;
    cudaGetSymbolAddress(&p, g_O2Th); O2Th = (__nv_bfloat16*)p;
    cudaGetSymbolAddress(&p, g_O2Tl); O2Tl = (__nv_bfloat16*)p;
    cudaGetSymbolAddress(&p, g_P1h);  P1h  = (__nv_bfloat16*)p;
    cudaGetSymbolAddress(&p, g_P1l);  P1l  = (__nv_bfloat16*)p;
    cudaGetSymbolAddress(&p, g_P2h);  P2h  = (__nv_bfloat16*)p;
    cudaGetSymbolAddress(&p, g_P2l);  P2l  = (__nv_bfloat16*)p;
    const int NS = BNCNT * 256;

    static cudaStream_t sA = nullptr, sB = nullptr, sZ = nullptr;
    static cudaEvent_t eFork, eZ, eL1, eL2, eX2T, eO1T, eO2T, eSc, eP1;
    static cudaEvent_t eA0, eA1, eA2, ePc;
    static int inited = 0;
    if (!inited) {
        cudaStreamCreateWithFlags(&sA, cudaStreamNonBlocking);
        cudaStreamCreateWithFlags(&sB, cudaStreamNonBlocking);
        cudaStreamCreateWithFlags(&sZ, cudaStreamNonBlocking);
        cudaEventCreateWithFlags(&eFork, cudaEventDisableTiming);
        cudaEventCreateWithFlags(&eZ,    cudaEventDisableTiming);
        cudaEventCreateWithFlags(&eL1,   cudaEventDisableTiming);
        cudaEventCreateWithFlags(&eL2,   cudaEventDisableTiming);
        cudaEventCreateWithFlags(&eX2T,  cudaEventDisableTiming);
        cudaEventCreateWithFlags(&eO1T,  cudaEventDisableTiming);
        cudaEventCreateWithFlags(&eO2T,  cudaEventDisableTiming);
        cudaEventCreateWithFlags(&eSc,   cudaEventDisableTiming);
        cudaEventCreateWithFlags(&eP1,   cudaEventDisableTiming);
        cudaEventCreateWithFlags(&eA0,   cudaEventDisableTiming);
        cudaEventCreateWithFlags(&eA1,   cudaEventDisableTiming);
        cudaEventCreateWithFlags(&eA2,   cudaEventDisableTiming);
        cudaEventCreateWithFlags(&ePc,   cudaEventDisableTiming);
        cudaFuncSetAttribute(score_mma, cudaFuncAttributeMaxDynamicSharedMemorySize, SMEM_BYTES);
        cudaFuncSetAttribute(av_mma,   cudaFuncAttributeMaxDynamicSharedMemorySize, SMEM_BYTES);
        cudaFuncSetAttribute(pconv_mma, cudaFuncAttributeMaxDynamicSharedMemorySize, PSMEM);
        cudaFuncSetAttribute(ln_kernel, cudaFuncAttributeMaxDynamicSharedMemorySize, 98304);
        inited = 1;
    }

    // fork auxiliary streams off the main (capture) stream
    cudaEventRecord(eFork, 0);
    cudaStreamWaitEvent(sA, eFork, 0);
    cudaStreamWaitEvent(sB, eFork, 0);
    cudaStreamWaitEvent(sZ, eFork, 0);

    // sZ: zero norm accumulators
    zero_kernel<<<128, 256, 0, sZ>>>();
    cudaEventRecord(eZ, sZ);

    // main (x1 branch): ln1
    ln_kernel<<<dim3(256, 4), 256, 98304, 0>>>(x1, ln1w, ln1b, x1ln, X1h, X1l);
    cudaEventRecord(eL1, 0);

    // sB (x2 branch): ln2
    ln_kernel<<<dim3(256, 4), 256, 98304, sB>>>(x2, ln2w, ln2b, x2ln, X2h, X2l);
    cudaEventRecord(eL2, sB);

    // sA: the two X transposes (+ norms 0 and 3)
    cudaStreamWaitEvent(sA, eZ, 0);
    cudaStreamWaitEvent(sA, eL1, 0);
    splitT_kernel<<<dim3(32, 384), dim3(32, 8), 0, sA>>>(x1ln, X1Th, X1Tl, 0, -1);
    cudaStreamWaitEvent(sA, eL2, 0);
    splitT_kernel<<<dim3(32, 384), dim3(32, 8), 0, sA>>>(x2ln, X2Th, X2Tl, -1, 3);
    cudaEventRecord(eX2T, sA);

    // main: x1 branch continues
    dw_kernel<<<dim3(64, 96, 4), 256, 0, 0>>>(x1ln, c11w, c11b, c12w, c12b, tmp);
    pconv_mma<<<dim3(128, 4), 256, PSMEM, 0>>>(tmp, projw, projb, out1, nullptr, nullptr, 1.f, O1h, O1l, 0);
    cudaStreamWaitEvent(0, eZ, 0);
    splitT_kernel<<<dim3(32, 384), dim3(32, 8), 0, 0>>>(out1, O1Th, O1Tl, 2, -1);   // 2=sq2 row out1
    cudaEventRecord(eO1T, 0);

    // sB: x2 branch continues
    dw_kernel<<<dim3(64, 96, 4), 256, 0, sB>>>(x2ln, c21w, c21b, c22w, c22b, tmp2);
    pconv_mma<<<dim3(128, 4), 256, PSMEM, sB>>>(tmp2, projw, projb, out2, nullptr, nullptr, 1.f, nullptr, nullptr, 0);
    cudaStreamWaitEvent(sB, eZ, 0);
    splitT_kernel<<<dim3(32, 384), dim3(32, 8), 0, sB>>>(out2, O2Th, O2Tl, -1, 1);  // 1=sq1 col out2
    cudaEventRecord(eO2T, sB);

    // sA: scale after all 4 norm contributors
    cudaStreamWaitEvent(sA, eO1T, 0);
    cudaStreamWaitEvent(sA, eO2T, 0);
    scale_kernel<<<128, 256, 0, sA>>>();
    cudaEventRecord(eSc, sA);

    // main: S2 = O1 @ X2T' — compute under sB's remaining memory work
    cudaStreamWaitEvent(0, eX2T, 0);
    score_mma<<<dim3(4, 32), 256, SMEM_BYTES, 0>>>(O1h, O1l, X2Th, X2Tl, S2);

    // sB: S1 = O2T @ X1' then softmax1 -> P1
    cudaStreamWaitEvent(sB, eL1, 0);
    score_mma<<<dim3(4, 32), 256, SMEM_BYTES, sB>>>(O2Th, O2Tl, X1h, X1l, S1);
    cudaStreamWaitEvent(sB, eSc, 0);
    softmax_kernel<<<dim3(64, 32), 128, 0, sB>>>(S1, sc + 1 * NS, sc + 0 * NS, P1h, P1l);
    cudaEventRecord(eP1, sB);

    // main: softmax2 -> P2
    cudaStreamWaitEvent(0, eSc, 0);
    softmax_kernel<<<dim3(64, 32), 128, 0, 0>>>(S2, sc + 2 * NS, sc + 3 * NS, P2h, P2l);
    cudaStreamWaitEvent(0, eP1, 0);

    // main: av in 4 batch chunks; final pconv chunks pipelined on sA
    av_mma<<<dim3(4, 12, 8), 256, SMEM_BYTES, 0>>>(P1h, P1l, X1Th, X1Tl, X2h, X2l, P2h, P2l,
                                                   O1Th, O1Tl, O2Th, O2Tl,
                                                   sc + 1 * NS, sc + 2 * NS, Mbuf, 0);
    cudaEventRecord(eA0, 0);
    av_mma<<<dim3(4, 12, 8), 256, SMEM_BYTES, 0>>>(P1h, P1l, X1Th, X1Tl, X2h, X2l, P2h, P2l,
                                                   O1Th, O1Tl, O2Th, O2Tl,
                                                   sc + 1 * NS, sc + 2 * NS, Mbuf, 8);
    cudaEventRecord(eA1, 0);
    av_mma<<<dim3(4, 12, 8), 256, SMEM_BYTES, 0>>>(P1h, P1l, X1Th, X1Tl, X2h, X2l, P2h, P2l,
                                                   O1Th, O1Tl, O2Th, O2Tl,
                                                   sc + 1 * NS, sc + 2 * NS, Mbuf, 16);
    cudaEventRecord(eA2, 0);
    av_mma<<<dim3(4, 12, 8), 256, SMEM_BYTES, 0>>>(P1h, P1l, X1Th, X1Tl, X2h, X2l, P2h, P2l,
                                                   O1Th, O1Tl, O2Th, O2Tl,
                                                   sc + 1 * NS, sc + 2 * NS, Mbuf, 24);

    // sA: pconv batches 0..2 as soon as their av chunk completes
    cudaStreamWaitEvent(sA, eA0, 0);
    pconv_mma<<<dim3(128, 1), 256, PSMEM, sA>>>(Mbuf, projw, projb, (float*)d_out,
                                                x1ln, x2ln, 2.f, nullptr, nullptr, 0);
    cudaStreamWaitEvent(sA, eA1, 0);
    pconv_mma<<<dim3(128, 1), 256, PSMEM, sA>>>(Mbuf, projw, projb, (float*)d_out,
                                                x1ln, x2ln, 2.f, nullptr, nullptr, 1);
    cudaStreamWaitEvent(sA, eA2, 0);
    pconv_mma<<<dim3(128, 1), 256, PSMEM, sA>>>(Mbuf, projw, projb, (float*)d_out,
                                                x1ln, x2ln, 2.f, nullptr, nullptr, 2);
    cudaEventRecord(ePc, sA);

    // main: final batch 3 in-stream after av chunk 3, then join sA
    pconv_mma<<<dim3(128, 1), 256, PSMEM, 0>>>(Mbuf, projw, projb, (float*)d_out,
                                               x1ln, x2ln, 2.f, nullptr, nullptr, 3);
    cudaStreamWaitEvent(0, ePc, 0);
}